// round 9
// baseline (speedup 1.0000x reference)
#include <cuda_runtime.h>
#include <math.h>

// Problem constants
#define BB 4
#define NN 2048
#define DIM 512
#define HEADS 8
#define DH 64
#define HIDDEN 512          // HEADS*DH
#define THC 1536            // 3*HIDDEN

// ---------------- scratch (device globals: allocation-free rule) ----------
__device__ float g_qkv[(size_t)BB * NN * THC];        // 48 MB
__device__ float g_q  [(size_t)BB * HEADS * NN * DH]; // 16 MB
__device__ float g_k  [(size_t)BB * HEADS * NN * DH]; // 16 MB
__device__ float g_v  [(size_t)BB * HEADS * NN * DH]; // 16 MB
__device__ float g_mid[(size_t)BB * NN * HIDDEN];     // 16 MB

// inv_freq[i] = 10000^(-2i/64) = 10^(-i/8), correctly-rounded fp32
__constant__ float c_invfreq[32] = {
    1.0f,
    0.74989420933245582f, 0.56234132519034907f, 0.42169650342858220f,
    0.31622776601683794f, 0.23713737056616552f, 0.17782794100389228f,
    0.13335214321633240f, 0.1f,
    0.074989420933245582f, 0.056234132519034907f, 0.042169650342858220f,
    0.031622776601683794f, 0.023713737056616552f, 0.017782794100389228f,
    0.013335214321633240f, 0.01f,
    0.0074989420933245582f, 0.0056234132519034907f, 0.0042169650342858220f,
    0.0031622776601683794f, 0.0023713737056616552f, 0.0017782794100389228f,
    0.0013335214321633240f, 0.001f,
    0.00074989420933245582f, 0.00056234132519034907f, 0.00042169650342858220f,
    0.00031622776601683794f, 0.00023713737056616552f, 0.00017782794100389228f,
    0.00013335214321633240f
};

// ---------------- tf32 helpers ----------------
__device__ __forceinline__ unsigned cvt_tf32(float f) {
    unsigned r;
    asm("cvt.rna.tf32.f32 %0, %1;" : "=r"(r) : "f"(f));
    return r;
}

__device__ __forceinline__ void mma_tf32(float c[4],
                                         unsigned a0, unsigned a1,
                                         unsigned a2, unsigned a3,
                                         unsigned b0, unsigned b1) {
    asm volatile(
        "mma.sync.aligned.m16n8k8.row.col.f32.tf32.tf32.f32 "
        "{%0,%1,%2,%3}, {%4,%5,%6,%7}, {%8,%9}, {%0,%1,%2,%3};\n"
        : "+f"(c[0]), "+f"(c[1]), "+f"(c[2]), "+f"(c[3])
        : "r"(a0), "r"(a1), "r"(a2), "r"(a3), "r"(b0), "r"(b1));
}

__device__ __forceinline__ void cp16(float* dst_smem, const float* src_gmem) {
    unsigned s = (unsigned)__cvta_generic_to_shared(dst_smem);
    asm volatile("cp.async.cg.shared.global [%0], [%1], 16;"
                 :: "r"(s), "l"(src_gmem));
}
__device__ __forceinline__ void cp_commit() {
    asm volatile("cp.async.commit_group;");
}
__device__ __forceinline__ void cp_wait1() {
    asm volatile("cp.async.wait_group 1;");
}

// =====================================================================
// Tensor-core GEMM: C[M,Nc] = A[M,K] @ B[K,Nc], fp32 in/out.
// USE3X=1: 3-term split tf32 (A_hi*B_hi + A_lo*B_hi + A_hi*B_lo) ~ fp32.
// USE3X=0: plain 1x tf32.
// Block 128m x 64n, 256 thr (8 warps x 16 rows), K-step 32.
// Fragment-major smem: slabs of 132 words; readers do LDS.128.
//   A slab (w,kk): word = (w*4+kk)*132 + lane*4 + reg
//   B slab (nt,p): word = BBASE + (nt*2+p)*132 + lane*4 + (kk&1)*2 + reg
// Register prefetch of next K32 tile; 2 barriers per K32.
// =====================================================================
#define APLANE (32 * 132)
#define BPLANE (16 * 132)

template<int USE3X>
__global__ __launch_bounds__(256, 2)
void mma_gemm(const float* __restrict__ A, const float* __restrict__ Bm,
              float* __restrict__ C, int M, int Nc, int K)
{
    extern __shared__ unsigned sm[];
    const int BBASE = USE3X ? 2 * APLANE : APLANE;

    const int tid  = threadIdx.x;
    const int lane = tid & 31;
    const int w    = tid >> 5;
    const int qg   = lane >> 2;
    const int q    = lane & 3;
    const int m0   = blockIdx.y * 128;
    const int n0   = blockIdx.x * 64;

    // A writer: thread owns row ar, k-half ks (16 cols)
    const int ar     = tid >> 1;
    const int ks     = (tid & 1) * 16;
    const int awbase = (ar >> 4) * 4 * 132;
    const int aqg    = ar & 7;
    const int arb    = ((ar & 15) >= 8) ? 1 : 0;
    // B writer: thread owns k-row kb, 8 n-cols from nc8
    const int kb  = tid >> 3;
    const int nc8 = (tid & 7) * 8;
    const int bwk = ((kb >> 3) & 1) * 2 + (((kb & 7) >= 4) ? 1 : 0);
    const int bwp = kb >> 4;

    float C_[8][4];
#pragma unroll
    for (int nt = 0; nt < 8; ++nt)
#pragma unroll
        for (int j = 0; j < 4; ++j) C_[nt][j] = 0.f;

    // prefetch tile 0 into registers
    float4 a_r[4];
    float4 b_r[2];
    {
        const float* ap = A + (size_t)(m0 + ar) * K + ks;
        a_r[0] = *(const float4*)ap;
        a_r[1] = *(const float4*)(ap + 4);
        a_r[2] = *(const float4*)(ap + 8);
        a_r[3] = *(const float4*)(ap + 12);
        const float* bp = Bm + (size_t)kb * Nc + n0 + nc8;
        b_r[0] = *(const float4*)bp;
        b_r[1] = *(const float4*)(bp + 4);
    }

    const int NK = K >> 5;
    for (int it = 0; it < NK; ++it) {
        // ---- scatter regs -> fragment-major smem (hi [+lo]) ----
#pragma unroll
        for (int j = 0; j < 4; ++j) {
            float vv[4] = {a_r[j].x, a_r[j].y, a_r[j].z, a_r[j].w};
#pragma unroll
            for (int c2 = 0; c2 < 4; ++c2) {
                int kc = ks + j * 4 + c2;
                int addr = awbase + (kc >> 3) * 132
                         + ((aqg << 2) + (kc & 3)) * 4
                         + arb + (((kc & 7) >= 4) ? 2 : 0);
                unsigned hi = cvt_tf32(vv[c2]);
                sm[addr] = hi;
                if (USE3X)
                    sm[APLANE + addr] = cvt_tf32(vv[c2] - __uint_as_float(hi));
            }
        }
#pragma unroll
        for (int j = 0; j < 2; ++j) {
            float vv[4] = {b_r[j].x, b_r[j].y, b_r[j].z, b_r[j].w};
#pragma unroll
            for (int c2 = 0; c2 < 4; ++c2) {
                int n = nc8 + j * 4 + c2;
                int addr = BBASE + (((n >> 3) << 1) + bwp) * 132
                         + (((n & 7) << 2) + (kb & 3)) * 4 + bwk;
                unsigned hi = cvt_tf32(vv[c2]);
                sm[addr] = hi;
                if (USE3X)
                    sm[addr + BPLANE] = cvt_tf32(vv[c2] - __uint_as_float(hi));
            }
        }
        __syncthreads();

        // ---- prefetch next tile (clamped re-load on last iter) ----
        {
            int itn = (it + 1 < NK) ? it + 1 : it;
            const float* ap = A + (size_t)(m0 + ar) * K + itn * 32 + ks;
            a_r[0] = *(const float4*)ap;
            a_r[1] = *(const float4*)(ap + 4);
            a_r[2] = *(const float4*)(ap + 8);
            a_r[3] = *(const float4*)(ap + 12);
            const float* bp = Bm + (size_t)(itn * 32 + kb) * Nc + n0 + nc8;
            b_r[0] = *(const float4*)bp;
            b_r[1] = *(const float4*)(bp + 4);
        }

        // ---- compute ----
        uint4 ahi[4], alo[4];
#pragma unroll
        for (int kk = 0; kk < 4; ++kk) {
            ahi[kk] = *(const uint4*)&sm[(w * 4 + kk) * 132 + lane * 4];
            if (USE3X)
                alo[kk] = *(const uint4*)&sm[APLANE + (w * 4 + kk) * 132 + lane * 4];
        }
#pragma unroll
        for (int nt = 0; nt < 8; ++nt) {
            const unsigned* bb = &sm[BBASE + nt * 2 * 132 + lane * 4];
            uint4 b0 = *(const uint4*)bb;
            uint4 b1 = *(const uint4*)(bb + 132);
            mma_tf32(C_[nt], ahi[0].x, ahi[0].y, ahi[0].z, ahi[0].w, b0.x, b0.y);
            mma_tf32(C_[nt], ahi[1].x, ahi[1].y, ahi[1].z, ahi[1].w, b0.z, b0.w);
            mma_tf32(C_[nt], ahi[2].x, ahi[2].y, ahi[2].z, ahi[2].w, b1.x, b1.y);
            mma_tf32(C_[nt], ahi[3].x, ahi[3].y, ahi[3].z, ahi[3].w, b1.z, b1.w);
            if (USE3X) {
                // lo(A) * hi(B)
                mma_tf32(C_[nt], alo[0].x, alo[0].y, alo[0].z, alo[0].w, b0.x, b0.y);
                mma_tf32(C_[nt], alo[1].x, alo[1].y, alo[1].z, alo[1].w, b0.z, b0.w);
                mma_tf32(C_[nt], alo[2].x, alo[2].y, alo[2].z, alo[2].w, b1.x, b1.y);
                mma_tf32(C_[nt], alo[3].x, alo[3].y, alo[3].z, alo[3].w, b1.z, b1.w);
                // hi(A) * lo(B)
                const unsigned* bl = bb + BPLANE;
                uint4 l0 = *(const uint4*)bl;
                uint4 l1 = *(const uint4*)(bl + 132);
                mma_tf32(C_[nt], ahi[0].x, ahi[0].y, ahi[0].z, ahi[0].w, l0.x, l0.y);
                mma_tf32(C_[nt], ahi[1].x, ahi[1].y, ahi[1].z, ahi[1].w, l0.z, l0.w);
                mma_tf32(C_[nt], ahi[2].x, ahi[2].y, ahi[2].z, ahi[2].w, l1.x, l1.y);
                mma_tf32(C_[nt], ahi[3].x, ahi[3].y, ahi[3].z, ahi[3].w, l1.z, l1.w);
            }
        }
        __syncthreads();
    }

    // ---- epilogue ----
#pragma unroll
    for (int nt = 0; nt < 8; ++nt) {
        int col = n0 + nt * 8 + 2 * q;
        size_t row = (size_t)(m0 + w * 16 + qg);
        *(float2*)&C[row * Nc + col]       = make_float2(C_[nt][0], C_[nt][1]);
        *(float2*)&C[(row + 8) * Nc + col] = make_float2(C_[nt][2], C_[nt][3]);
    }
}

#define GEMM_SMEM_3X (4 * 2 * (APLANE + BPLANE))   // 50688 B
#define GEMM_SMEM_1X (4 * (APLANE + BPLANE))       // 25344 B

// =====================================================================
// QKV split + head reshape + rotary (+ q scale).
// =====================================================================
__global__ __launch_bounds__(256)
void qkv_transform()
{
    const int idx  = blockIdx.x * 256 + threadIdx.x;
    const int pair = idx & 31;
    const int n    = (idx >> 5) & (NN - 1);
    const int bh   = idx >> 16;
    const int b    = bh >> 3;
    const int h    = bh & 7;

    const float* src = g_qkv + (size_t)(b * NN + n) * THC;
    const int col = h * DH + pair * 2;

    float2 qv = *(const float2*)&src[col];
    float2 kv = *(const float2*)&src[HIDDEN + col];
    float2 vv = *(const float2*)&src[2 * HIDDEN + col];

    float fr = (float)n * c_invfreq[pair];
    float sn, cs;
    sincosf(fr, &sn, &cs);

    const float scale = 0.125f;
    float oq0 = (qv.x * cs - qv.y * sn) * scale;
    float oq1 = (qv.y * cs + qv.x * sn) * scale;
    float ok0 = kv.x * cs - kv.y * sn;
    float ok1 = kv.y * cs + kv.x * sn;

    size_t o = ((size_t)bh * NN + n) * DH + pair * 2;
    g_q[o] = oq0; g_q[o + 1] = oq1;
    g_k[o] = ok0; g_k[o + 1] = ok1;
    g_v[o] = vv.x; g_v[o + 1] = vv.y;
}

// =====================================================================
// Fused flash attention, tf32 tensor cores, cp.async pipelined.
// (unchanged from previous round)
// =====================================================================
#define TSTRIDE 656
#define SSTRIDE 68
#define STG_CHUNK (32 * SSTRIDE)

__global__ __launch_bounds__(256, 2)
void attn_tf32(const float* __restrict__ bias)
{
    extern __shared__ unsigned smem_u[];
    unsigned* KF  = smem_u;                      // [2][4*TSTRIDE]
    unsigned* VF  = smem_u + 2 * 4 * TSTRIDE;    // [2][4*TSTRIDE]
    float*    stK = (float*)(smem_u + 4 * 4 * TSTRIDE);  // [2][32*68]
    float*    stV = stK + 2 * STG_CHUNK;                  // [2][32*68]

    const int tid  = threadIdx.x;
    const int lane = tid & 31;
    const int w    = tid >> 5;
    const int qg   = lane >> 2;
    const int q    = lane & 3;
    const int qblk = blockIdx.x * 128;
    const int h    = blockIdx.y;
    const int b    = blockIdx.z;
    const size_t base = ((size_t)(b * HEADS + h)) * NN * DH;
    const float* gk = g_k + base;
    const float* gv = g_v + base;
    const float* biasw = bias + (size_t)h * NN * NN
                              + (size_t)(qblk + w * 16) * NN;

    const int wr  = tid >> 3;
    const int wc8 = (tid & 7) * 8;
    const int wt  = wr >> 3;
    const int wqg = wr & 7;
    const int wq  = wr & 3;
    const int whf = (wr >> 2) & 1;
    const int wkc = tid & 7;
    const int kdst = wt * TSTRIDE + wqg * 80 + (wqg >= 4 ? 8 : 0) + wkc * 2;
    const int vdst = wt * TSTRIDE + wq * 20 + wkc * 2 + whf;
    const int stoff = wr * SSTRIDE + wc8;
    const int rb = lane * 20 + (lane >= 16 ? 8 : 0);

    unsigned qa[8][4];
    {
        const float* Qp = g_q + base + (size_t)(qblk + w * 16) * DH;
#pragma unroll
        for (int kc = 0; kc < 8; ++kc) {
            qa[kc][0] = cvt_tf32(Qp[(size_t)qg       * DH + kc * 8 + q]);
            qa[kc][1] = cvt_tf32(Qp[(size_t)(qg + 8) * DH + kc * 8 + q]);
            qa[kc][2] = cvt_tf32(Qp[(size_t)qg       * DH + kc * 8 + q + 4]);
            qa[kc][3] = cvt_tf32(Qp[(size_t)(qg + 8) * DH + kc * 8 + q + 4]);
        }
    }

    cp16(&stK[stoff], gk + (size_t)wr * DH + wc8);
    cp16(&stK[stoff + 4], gk + (size_t)wr * DH + wc8 + 4);
    cp16(&stV[stoff], gv + (size_t)wr * DH + wc8);
    cp16(&stV[stoff + 4], gv + (size_t)wr * DH + wc8 + 4);
    cp_commit();
    cp16(&stK[STG_CHUNK + stoff], gk + (size_t)(32 + wr) * DH + wc8);
    cp16(&stK[STG_CHUNK + stoff + 4], gk + (size_t)(32 + wr) * DH + wc8 + 4);
    cp16(&stV[STG_CHUNK + stoff], gv + (size_t)(32 + wr) * DH + wc8);
    cp16(&stV[STG_CHUNK + stoff + 4], gv + (size_t)(32 + wr) * DH + wc8 + 4);
    cp_commit();

    float S[4][4];
    cp_wait1();
    {
#pragma unroll
        for (int t = 0; t < 4; ++t) {
            float2 blo = *(const float2*)&biasw[(size_t)qg       * NN + t * 8 + 2 * q];
            float2 bhi = *(const float2*)&biasw[(size_t)(qg + 8) * NN + t * 8 + 2 * q];
            S[t][0] = blo.x; S[t][1] = blo.y;
            S[t][2] = bhi.x; S[t][3] = bhi.y;
        }
        float4 k0 = *(const float4*)&stK[stoff];
        float4 k1 = *(const float4*)&stK[stoff + 4];
        float4 v0 = *(const float4*)&stV[stoff];
        float4 v1 = *(const float4*)&stV[stoff + 4];
        unsigned* kf = KF;
        unsigned* vf = VF;
        kf[kdst +  0] = cvt_tf32(k0.x); kf[kdst + 20] = cvt_tf32(k0.y);
        kf[kdst + 40] = cvt_tf32(k0.z); kf[kdst + 60] = cvt_tf32(k0.w);
        kf[kdst +  1] = cvt_tf32(k1.x); kf[kdst + 21] = cvt_tf32(k1.y);
        kf[kdst + 41] = cvt_tf32(k1.z); kf[kdst + 61] = cvt_tf32(k1.w);
        vf[vdst +   0]     = cvt_tf32(v0.x);
        vf[vdst +  80]     = cvt_tf32(v0.y);
        vf[vdst + 160]     = cvt_tf32(v0.z);
        vf[vdst + 240]     = cvt_tf32(v0.w);
        vf[vdst + 320 + 8] = cvt_tf32(v1.x);
        vf[vdst + 400 + 8] = cvt_tf32(v1.y);
        vf[vdst + 480 + 8] = cvt_tf32(v1.z);
        vf[vdst + 560 + 8] = cvt_tf32(v1.w);
    }
    __syncthreads();

    float O[8][4];
#pragma unroll
    for (int n = 0; n < 8; ++n)
#pragma unroll
        for (int j = 0; j < 4; ++j) O[n][j] = 0.f;
    float m0 = -INFINITY, m1 = -INFINITY, l0 = 0.f, l1 = 0.f;

    for (int j = 0; j < 64; ++j) {
        const int p = j & 1;

        const unsigned* kfp = KF + p * (4 * TSTRIDE);
#pragma unroll
        for (int t = 0; t < 4; ++t) {
            const uint4* kk = (const uint4*)&kfp[t * TSTRIDE + rb];
            uint4 k0 = kk[0], k1 = kk[1], k2 = kk[2], k3 = kk[3];
            mma_tf32(S[t], qa[0][0], qa[0][1], qa[0][2], qa[0][3], k0.x, k0.y);
            mma_tf32(S[t], qa[1][0], qa[1][1], qa[1][2], qa[1][3], k0.z, k0.w);
            mma_tf32(S[t], qa[2][0], qa[2][1], qa[2][2], qa[2][3], k1.x, k1.y);
            mma_tf32(S[t], qa[3][0], qa[3][1], qa[3][2], qa[3][3], k1.z, k1.w);
            mma_tf32(S[t], qa[4][0], qa[4][1], qa[4][2], qa[4][3], k2.x, k2.y);
            mma_tf32(S[t], qa[5][0], qa[5][1], qa[5][2], qa[5][3], k2.z, k2.w);
            mma_tf32(S[t], qa[6][0], qa[6][1], qa[6][2], qa[6][3], k3.x, k3.y);
            mma_tf32(S[t], qa[7][0], qa[7][1], qa[7][2], qa[7][3], k3.z, k3.w);
        }

        float cm0 = -INFINITY, cm1 = -INFINITY;
#pragma unroll
        for (int t = 0; t < 4; ++t) {
            cm0 = fmaxf(cm0, fmaxf(S[t][0], S[t][1]));
            cm1 = fmaxf(cm1, fmaxf(S[t][2], S[t][3]));
        }
        cm0 = fmaxf(cm0, __shfl_xor_sync(0xffffffffu, cm0, 1));
        cm0 = fmaxf(cm0, __shfl_xor_sync(0xffffffffu, cm0, 2));
        cm1 = fmaxf(cm1, __shfl_xor_sync(0xffffffffu, cm1, 1));
        cm1 = fmaxf(cm1, __shfl_xor_sync(0xffffffffu, cm1, 2));

        float mn0 = fmaxf(m0, cm0), mn1 = fmaxf(m1, cm1);
        float al0 = __expf(m0 - mn0), al1 = __expf(m1 - mn1);
        m0 = mn0; m1 = mn1;

        float s0 = 0.f, s1 = 0.f;
#pragma unroll
        for (int t = 0; t < 4; ++t) {
            S[t][0] = __expf(S[t][0] - mn0);
            S[t][1] = __expf(S[t][1] - mn0);
            S[t][2] = __expf(S[t][2] - mn1);
            S[t][3] = __expf(S[t][3] - mn1);
            s0 += S[t][0] + S[t][1];
            s1 += S[t][2] + S[t][3];
        }
        s0 += __shfl_xor_sync(0xffffffffu, s0, 1);
        s0 += __shfl_xor_sync(0xffffffffu, s0, 2);
        s1 += __shfl_xor_sync(0xffffffffu, s1, 1);
        s1 += __shfl_xor_sync(0xffffffffu, s1, 2);
        l0 = l0 * al0 + s0;
        l1 = l1 * al1 + s1;
#pragma unroll
        for (int n = 0; n < 8; ++n) {
            O[n][0] *= al0; O[n][1] *= al0;
            O[n][2] *= al1; O[n][3] *= al1;
        }

        const unsigned* vfp = VF + p * (4 * TSTRIDE);
        const int srcA = (lane & ~3) | (q >> 1);
        const int srcB = srcA | 2;
#pragma unroll
        for (int t = 0; t < 4; ++t) {
            unsigned p0 = cvt_tf32(S[t][0]);
            unsigned p1 = cvt_tf32(S[t][1]);
            unsigned p2 = cvt_tf32(S[t][2]);
            unsigned p3 = cvt_tf32(S[t][3]);
            unsigned u0 = __shfl_sync(0xffffffffu, p0, srcA);
            unsigned u1 = __shfl_sync(0xffffffffu, p1, srcA);
            unsigned v0s = __shfl_sync(0xffffffffu, p0, srcB);
            unsigned v1s = __shfl_sync(0xffffffffu, p1, srcB);
            unsigned w0 = __shfl_sync(0xffffffffu, p2, srcA);
            unsigned w1 = __shfl_sync(0xffffffffu, p3, srcA);
            unsigned x0 = __shfl_sync(0xffffffffu, p2, srcB);
            unsigned x1 = __shfl_sync(0xffffffffu, p3, srcB);
            unsigned a0 = (q & 1) ? u1 : u0;
            unsigned a1 = (q & 1) ? w1 : w0;
            unsigned a2 = (q & 1) ? v1s : v0s;
            unsigned a3 = (q & 1) ? x1 : x0;
            const uint4* vv = (const uint4*)&vfp[t * TSTRIDE + rb];
            uint4 v0 = vv[0], v1 = vv[1], v2 = vv[2], v3 = vv[3];
            mma_tf32(O[0], a0, a1, a2, a3, v0.x, v0.y);
            mma_tf32(O[1], a0, a1, a2, a3, v0.z, v0.w);
            mma_tf32(O[2], a0, a1, a2, a3, v1.x, v1.y);
            mma_tf32(O[3], a0, a1, a2, a3, v1.z, v1.w);
            mma_tf32(O[4], a0, a1, a2, a3, v2.x, v2.y);
            mma_tf32(O[5], a0, a1, a2, a3, v2.z, v2.w);
            mma_tf32(O[6], a0, a1, a2, a3, v3.x, v3.y);
            mma_tf32(O[7], a0, a1, a2, a3, v3.z, v3.w);
        }

        {
            const int jc = (j + 2 < 64) ? j + 2 : 63;
            const size_t roff = (size_t)(jc * 32 + wr) * DH + wc8;
            float* sk = &stK[p * STG_CHUNK + stoff];
            float* sv = &stV[p * STG_CHUNK + stoff];
            cp16(sk,     gk + roff);
            cp16(sk + 4, gk + roff + 4);
            cp16(sv,     gv + roff);
            cp16(sv + 4, gv + roff + 4);
            cp_commit();
        }
        cp_wait1();

        {
            const int jb = (j + 1 < 64) ? j + 1 : 63;
            const int j0n = jb * 32;
#pragma unroll
            for (int t = 0; t < 4; ++t) {
                float2 blo = *(const float2*)
                    &biasw[(size_t)qg       * NN + j0n + t * 8 + 2 * q];
                float2 bhi = *(const float2*)
                    &biasw[(size_t)(qg + 8) * NN + j0n + t * 8 + 2 * q];
                S[t][0] = blo.x; S[t][1] = blo.y;
                S[t][2] = bhi.x; S[t][3] = bhi.y;
            }
        }

        {
            const int pn = p ^ 1;
            const float* sk = &stK[pn * STG_CHUNK + stoff];
            const float* sv = &stV[pn * STG_CHUNK + stoff];
            float4 k0 = *(const float4*)sk;
            float4 k1 = *(const float4*)(sk + 4);
            float4 v0 = *(const float4*)sv;
            float4 v1 = *(const float4*)(sv + 4);
            unsigned* kf = KF + pn * (4 * TSTRIDE);
            unsigned* vf = VF + pn * (4 * TSTRIDE);
            kf[kdst +  0] = cvt_tf32(k0.x); kf[kdst + 20] = cvt_tf32(k0.y);
            kf[kdst + 40] = cvt_tf32(k0.z); kf[kdst + 60] = cvt_tf32(k0.w);
            kf[kdst +  1] = cvt_tf32(k1.x); kf[kdst + 21] = cvt_tf32(k1.y);
            kf[kdst + 41] = cvt_tf32(k1.z); kf[kdst + 61] = cvt_tf32(k1.w);
            vf[vdst +   0]     = cvt_tf32(v0.x);
            vf[vdst +  80]     = cvt_tf32(v0.y);
            vf[vdst + 160]     = cvt_tf32(v0.z);
            vf[vdst + 240]     = cvt_tf32(v0.w);
            vf[vdst + 320 + 8] = cvt_tf32(v1.x);
            vf[vdst + 400 + 8] = cvt_tf32(v1.y);
            vf[vdst + 480 + 8] = cvt_tf32(v1.z);
            vf[vdst + 560 + 8] = cvt_tf32(v1.w);
        }
        __syncthreads();
    }

    const float il0 = 1.f / l0, il1 = 1.f / l1;
    const int row0 = qblk + w * 16 + qg;
    const int row1 = row0 + 8;
#pragma unroll
    for (int n = 0; n < 8; ++n) {
        float2 olo = make_float2(O[n][0] * il0, O[n][1] * il0);
        float2 ohi = make_float2(O[n][2] * il1, O[n][3] * il1);
        *(float2*)&g_mid[(size_t)(b * NN + row0) * HIDDEN
                         + h * DH + n * 8 + 2 * q] = olo;
        *(float2*)&g_mid[(size_t)(b * NN + row1) * HIDDEN
                         + h * DH + n * 8 + 2 * q] = ohi;
    }
}

#define ATTN_SMEM (4 * (4 * 4 * TSTRIDE + 4 * STG_CHUNK))

// =====================================================================
extern "C" void kernel_launch(void* const* d_in, const int* in_sizes, int n_in,
                              void* d_out, int out_size)
{
    const float *x = nullptr, *bias = nullptr, *wqkv = nullptr, *wout = nullptr;
    for (int i = 0; i < n_in; ++i) {
        switch (in_sizes[i]) {
            case 4194304:  x    = (const float*)d_in[i]; break;  // x [4,2048,512]
            case 33554432: bias = (const float*)d_in[i]; break;  // pos_bias [8,2048,2048]
            case 786432:   wqkv = (const float*)d_in[i]; break;  // W_qkv [512,1536]
            case 262144:   wout = (const float*)d_in[i]; break;  // W_out [512,512]
        }
    }

    void *p_qkv = nullptr, *p_mid = nullptr;
    cudaGetSymbolAddress(&p_qkv, g_qkv);
    cudaGetSymbolAddress(&p_mid, g_mid);

    // opt-in to >48KB dynamic smem (non-stream calls: capture-safe)
    cudaFuncSetAttribute(attn_tf32,
                         cudaFuncAttributeMaxDynamicSharedMemorySize,
                         ATTN_SMEM);
    cudaFuncSetAttribute(mma_gemm<1>,
                         cudaFuncAttributeMaxDynamicSharedMemorySize,
                         GEMM_SMEM_3X);
    cudaFuncSetAttribute(mma_gemm<0>,
                         cudaFuncAttributeMaxDynamicSharedMemorySize,
                         GEMM_SMEM_1X);

    // 1) qkv = x @ W_qkv  (3-term split tf32 ~ fp32 accuracy)
    mma_gemm<1><<<dim3(THC / 64, (BB * NN) / 128), 256, GEMM_SMEM_3X>>>(
        x, wqkv, (float*)p_qkv, BB * NN, THC, DIM);

    // 2) split + rotary + scale
    qkv_transform<<<(BB * HEADS * NN * 32) / 256, 256>>>();

    // 3) fused flash attention (tf32 tensor cores, cp.async pipelined)
    attn_tf32<<<dim3(NN / 128, HEADS, BB), 256, ATTN_SMEM>>>(bias);

    // 4) out = mid @ W_out  (1x tf32; terminal, error adds in quadrature)
    mma_gemm<0><<<dim3(DIM / 64, (BB * NN) / 128), 256, GEMM_SMEM_1X>>>(
        (const float*)p_mid, wout, (float*)d_out, BB * NN, DIM, HIDDEN);
}

// round 10
// speedup vs baseline: 1.1237x; 1.1237x over previous
#include <cuda_runtime.h>
#include <math.h>

// Problem constants
#define BB 4
#define NN 2048
#define DIM 512
#define HEADS 8
#define DH 64
#define HIDDEN 512          // HEADS*DH
#define THC 1536            // 3*HIDDEN

// ---------------- scratch (device globals: allocation-free rule) ----------
__device__ float g_qkv[(size_t)BB * NN * THC];        // 48 MB
__device__ float g_q  [(size_t)BB * HEADS * NN * DH]; // 16 MB
__device__ float g_k  [(size_t)BB * HEADS * NN * DH]; // 16 MB
__device__ float g_v  [(size_t)BB * HEADS * NN * DH]; // 16 MB
__device__ float g_mid[(size_t)BB * NN * HIDDEN];     // 16 MB

// inv_freq[i] = 10000^(-2i/64) = 10^(-i/8), correctly-rounded fp32
__constant__ float c_invfreq[32] = {
    1.0f,
    0.74989420933245582f, 0.56234132519034907f, 0.42169650342858220f,
    0.31622776601683794f, 0.23713737056616552f, 0.17782794100389228f,
    0.13335214321633240f, 0.1f,
    0.074989420933245582f, 0.056234132519034907f, 0.042169650342858220f,
    0.031622776601683794f, 0.023713737056616552f, 0.017782794100389228f,
    0.013335214321633240f, 0.01f,
    0.0074989420933245582f, 0.0056234132519034907f, 0.0042169650342858220f,
    0.0031622776601683794f, 0.0023713737056616552f, 0.0017782794100389228f,
    0.0013335214321633240f, 0.001f,
    0.00074989420933245582f, 0.00056234132519034907f, 0.00042169650342858220f,
    0.00031622776601683794f, 0.00023713737056616552f, 0.00017782794100389228f,
    0.00013335214321633240f
};

// ---------------- tf32 / packed-f32 helpers ----------------
__device__ __forceinline__ unsigned cvt_tf32(float f) {
    unsigned r;
    asm("cvt.rna.tf32.f32 %0, %1;" : "=r"(r) : "f"(f));
    return r;
}

__device__ __forceinline__ void mma_tf32(float c[4],
                                         unsigned a0, unsigned a1,
                                         unsigned a2, unsigned a3,
                                         unsigned b0, unsigned b1) {
    asm volatile(
        "mma.sync.aligned.m16n8k8.row.col.f32.tf32.tf32.f32 "
        "{%0,%1,%2,%3}, {%4,%5,%6,%7}, {%8,%9}, {%0,%1,%2,%3};\n"
        : "+f"(c[0]), "+f"(c[1]), "+f"(c[2]), "+f"(c[3])
        : "r"(a0), "r"(a1), "r"(a2), "r"(a3), "r"(b0), "r"(b1));
}

__device__ __forceinline__ unsigned long long pack_dup(float v) {
    unsigned long long d;
    unsigned u = __float_as_uint(v);
    asm("mov.b64 %0, {%1, %1};" : "=l"(d) : "r"(u));
    return d;
}
__device__ __forceinline__ void ffma2(unsigned long long& acc,
                                      unsigned long long a,
                                      unsigned long long b) {
    asm("fma.rn.f32x2 %0, %1, %2, %0;" : "+l"(acc) : "l"(a), "l"(b));
}

__device__ __forceinline__ void cp16(float* dst_smem, const float* src_gmem) {
    unsigned s = (unsigned)__cvta_generic_to_shared(dst_smem);
    asm volatile("cp.async.cg.shared.global [%0], [%1], 16;"
                 :: "r"(s), "l"(src_gmem));
}
__device__ __forceinline__ void cp_commit() {
    asm volatile("cp.async.commit_group;");
}
__device__ __forceinline__ void cp_wait0() {
    asm volatile("cp.async.wait_group 0;");
}
__device__ __forceinline__ void cp_wait1() {
    asm volatile("cp.async.wait_group 1;");
}

// =====================================================================
// SGEMM (fp32-exact, packed FFMA2), cp.async double-buffered.
// C[M,Nc] = A[M,K] @ B[K,Nc]. Block 128x64, BK=16, 256 threads,
// 8x4 per thread (rows paired in f32x2). One barrier per K16 iter:
//   iter it: cp.async B(it+1)->Bs[p^1] | compute(As[p],Bs[p]) |
//            STS A(it+1)->As[p^1] (regs from prev iter) | LDG A(it+2) |
//            wait_group(0) | __syncthreads.
// =====================================================================
__global__ __launch_bounds__(256)
void sgemm128(const float* __restrict__ A, const float* __restrict__ Bm,
              float* __restrict__ C, int M, int Nc, int K)
{
    __shared__ float As[2][16 * 134];
    __shared__ float Bs[2][16 * 64];

    const int tid = threadIdx.x;
    const int tx  = tid & 15;
    const int ty  = tid >> 4;
    const int m0  = blockIdx.y * 128;
    const int n0  = blockIdx.x * 64;

    unsigned long long acc[4][4];
#pragma unroll
    for (int j = 0; j < 4; ++j)
#pragma unroll
        for (int p = 0; p < 4; ++p) acc[j][p] = 0ULL;

    const int ar  = tid >> 1;          // 0..127 (A row)
    const int ks  = (tid & 1) * 8;     // k-half: 0 or 8
    const int kb  = tid >> 4;          // 0..15 (B k-row)
    const int bc4 = (tid & 15) * 4;

    const float* Arow = A + (size_t)(m0 + ar) * K + ks;

    float4 a0, a1;
    // ---- prologue ----
    a0 = *(const float4*)Arow;
    a1 = *(const float4*)(Arow + 4);
    cp16(&Bs[0][kb * 64 + bc4], &Bm[(size_t)kb * Nc + n0 + bc4]);
    cp_commit();
    {
        float* dst = &As[0][ks * 134 + ar];
        dst[0 * 134] = a0.x; dst[1 * 134] = a0.y;
        dst[2 * 134] = a0.z; dst[3 * 134] = a0.w;
        dst[4 * 134] = a1.x; dst[5 * 134] = a1.y;
        dst[6 * 134] = a1.z; dst[7 * 134] = a1.w;
    }
    a0 = *(const float4*)(Arow + 16);
    a1 = *(const float4*)(Arow + 20);
    cp_wait0();
    __syncthreads();

    const int NK = K >> 4;
    for (int it = 0; it < NK; ++it) {
        const int p = it & 1;

        // cp.async B(it+1) into the idle buffer (hidden under compute)
        if (it + 1 < NK) {
            cp16(&Bs[p ^ 1][kb * 64 + bc4],
                 &Bm[(size_t)((it + 1) * 16 + kb) * Nc + n0 + bc4]);
            cp_commit();
        }

        // ---- compute tile it ----
#pragma unroll
        for (int k = 0; k < 16; ++k) {
            const float* arow = &As[p][k * 134 + ty * 8];
            unsigned long long ap0 = *(const unsigned long long*)(arow + 0);
            unsigned long long ap1 = *(const unsigned long long*)(arow + 2);
            unsigned long long ap2 = *(const unsigned long long*)(arow + 4);
            unsigned long long ap3 = *(const unsigned long long*)(arow + 6);
            float4 b = *(const float4*)&Bs[p][k * 64 + (tx << 2)];
            unsigned long long b0 = pack_dup(b.x);
            unsigned long long b1 = pack_dup(b.y);
            unsigned long long b2 = pack_dup(b.z);
            unsigned long long b3 = pack_dup(b.w);
            ffma2(acc[0][0], ap0, b0); ffma2(acc[0][1], ap1, b0);
            ffma2(acc[0][2], ap2, b0); ffma2(acc[0][3], ap3, b0);
            ffma2(acc[1][0], ap0, b1); ffma2(acc[1][1], ap1, b1);
            ffma2(acc[1][2], ap2, b1); ffma2(acc[1][3], ap3, b1);
            ffma2(acc[2][0], ap0, b2); ffma2(acc[2][1], ap1, b2);
            ffma2(acc[2][2], ap2, b2); ffma2(acc[2][3], ap3, b2);
            ffma2(acc[3][0], ap0, b3); ffma2(acc[3][1], ap1, b3);
            ffma2(acc[3][2], ap2, b3); ffma2(acc[3][3], ap3, b3);
        }

        if (it + 1 < NK) {
            // STS A(it+1) (regs loaded last iter) into idle buffer
            float* dst = &As[p ^ 1][ks * 134 + ar];
            dst[0 * 134] = a0.x; dst[1 * 134] = a0.y;
            dst[2 * 134] = a0.z; dst[3 * 134] = a0.w;
            dst[4 * 134] = a1.x; dst[5 * 134] = a1.y;
            dst[6 * 134] = a1.z; dst[7 * 134] = a1.w;
            // LDG A(it+2)
            if (it + 2 < NK) {
                a0 = *(const float4*)(Arow + (it + 2) * 16);
                a1 = *(const float4*)(Arow + (it + 2) * 16 + 4);
            }
            cp_wait0();
            __syncthreads();
        }
    }

    // ---- epilogue ----
#pragma unroll
    for (int p = 0; p < 4; ++p) {
        float4 lo, hi;
        lo.x = __uint_as_float((unsigned)acc[0][p]);
        lo.y = __uint_as_float((unsigned)acc[1][p]);
        lo.z = __uint_as_float((unsigned)acc[2][p]);
        lo.w = __uint_as_float((unsigned)acc[3][p]);
        hi.x = __uint_as_float((unsigned)(acc[0][p] >> 32));
        hi.y = __uint_as_float((unsigned)(acc[1][p] >> 32));
        hi.z = __uint_as_float((unsigned)(acc[2][p] >> 32));
        hi.w = __uint_as_float((unsigned)(acc[3][p] >> 32));
        size_t r = (size_t)(m0 + ty * 8 + 2 * p);
        *(float4*)&C[r * Nc + n0 + (tx << 2)]       = lo;
        *(float4*)&C[(r + 1) * Nc + n0 + (tx << 2)] = hi;
    }
}

// =====================================================================
// Tensor-core GEMM (1x tf32) for the terminal projection — measured
// 83us, error contribution ~2.9e-4 in quadrature (measured R9).
// =====================================================================
#define APLANE (32 * 132)
#define BPLANE (16 * 132)

__global__ __launch_bounds__(256, 2)
void mma_gemm1x(const float* __restrict__ A, const float* __restrict__ Bm,
                float* __restrict__ C, int M, int Nc, int K)
{
    extern __shared__ unsigned sm[];
    const int BBASE = APLANE;

    const int tid  = threadIdx.x;
    const int lane = tid & 31;
    const int w    = tid >> 5;
    const int qg   = lane >> 2;
    const int q    = lane & 3;
    const int m0   = blockIdx.y * 128;
    const int n0   = blockIdx.x * 64;

    const int ar     = tid >> 1;
    const int ks     = (tid & 1) * 16;
    const int awbase = (ar >> 4) * 4 * 132;
    const int aqg    = ar & 7;
    const int arb    = ((ar & 15) >= 8) ? 1 : 0;
    const int kb  = tid >> 3;
    const int nc8 = (tid & 7) * 8;
    const int bwk = ((kb >> 3) & 1) * 2 + (((kb & 7) >= 4) ? 1 : 0);
    const int bwp = kb >> 4;

    float C_[8][4];
#pragma unroll
    for (int nt = 0; nt < 8; ++nt)
#pragma unroll
        for (int j = 0; j < 4; ++j) C_[nt][j] = 0.f;

    float4 a_r[4];
    float4 b_r[2];
    {
        const float* ap = A + (size_t)(m0 + ar) * K + ks;
        a_r[0] = *(const float4*)ap;
        a_r[1] = *(const float4*)(ap + 4);
        a_r[2] = *(const float4*)(ap + 8);
        a_r[3] = *(const float4*)(ap + 12);
        const float* bp = Bm + (size_t)kb * Nc + n0 + nc8;
        b_r[0] = *(const float4*)bp;
        b_r[1] = *(const float4*)(bp + 4);
    }

    const int NK = K >> 5;
    for (int it = 0; it < NK; ++it) {
#pragma unroll
        for (int j = 0; j < 4; ++j) {
            float vv[4] = {a_r[j].x, a_r[j].y, a_r[j].z, a_r[j].w};
#pragma unroll
            for (int c2 = 0; c2 < 4; ++c2) {
                int kc = ks + j * 4 + c2;
                int addr = awbase + (kc >> 3) * 132
                         + ((aqg << 2) + (kc & 3)) * 4
                         + arb + (((kc & 7) >= 4) ? 2 : 0);
                sm[addr] = cvt_tf32(vv[c2]);
            }
        }
#pragma unroll
        for (int j = 0; j < 2; ++j) {
            float vv[4] = {b_r[j].x, b_r[j].y, b_r[j].z, b_r[j].w};
#pragma unroll
            for (int c2 = 0; c2 < 4; ++c2) {
                int n = nc8 + j * 4 + c2;
                int addr = BBASE + (((n >> 3) << 1) + bwp) * 132
                         + (((n & 7) << 2) + (kb & 3)) * 4 + bwk;
                sm[addr] = cvt_tf32(vv[c2]);
            }
        }
        __syncthreads();

        {
            int itn = (it + 1 < NK) ? it + 1 : it;
            const float* ap = A + (size_t)(m0 + ar) * K + itn * 32 + ks;
            a_r[0] = *(const float4*)ap;
            a_r[1] = *(const float4*)(ap + 4);
            a_r[2] = *(const float4*)(ap + 8);
            a_r[3] = *(const float4*)(ap + 12);
            const float* bp = Bm + (size_t)(itn * 32 + kb) * Nc + n0 + nc8;
            b_r[0] = *(const float4*)bp;
            b_r[1] = *(const float4*)(bp + 4);
        }

        uint4 ahi[4];
#pragma unroll
        for (int kk = 0; kk < 4; ++kk)
            ahi[kk] = *(const uint4*)&sm[(w * 4 + kk) * 132 + lane * 4];
#pragma unroll
        for (int nt = 0; nt < 8; ++nt) {
            const unsigned* bb = &sm[BBASE + nt * 2 * 132 + lane * 4];
            uint4 b0 = *(const uint4*)bb;
            uint4 b1 = *(const uint4*)(bb + 132);
            mma_tf32(C_[nt], ahi[0].x, ahi[0].y, ahi[0].z, ahi[0].w, b0.x, b0.y);
            mma_tf32(C_[nt], ahi[1].x, ahi[1].y, ahi[1].z, ahi[1].w, b0.z, b0.w);
            mma_tf32(C_[nt], ahi[2].x, ahi[2].y, ahi[2].z, ahi[2].w, b1.x, b1.y);
            mma_tf32(C_[nt], ahi[3].x, ahi[3].y, ahi[3].z, ahi[3].w, b1.z, b1.w);
        }
        __syncthreads();
    }

#pragma unroll
    for (int nt = 0; nt < 8; ++nt) {
        int col = n0 + nt * 8 + 2 * q;
        size_t row = (size_t)(m0 + w * 16 + qg);
        *(float2*)&C[row * Nc + col]       = make_float2(C_[nt][0], C_[nt][1]);
        *(float2*)&C[(row + 8) * Nc + col] = make_float2(C_[nt][2], C_[nt][3]);
    }
}

#define GEMM_SMEM_1X (4 * (APLANE + BPLANE))       // 25344 B

// =====================================================================
// QKV split + head reshape + rotary (+ q scale).
// =====================================================================
__global__ __launch_bounds__(256)
void qkv_transform()
{
    const int idx  = blockIdx.x * 256 + threadIdx.x;
    const int pair = idx & 31;
    const int n    = (idx >> 5) & (NN - 1);
    const int bh   = idx >> 16;
    const int b    = bh >> 3;
    const int h    = bh & 7;

    const float* src = g_qkv + (size_t)(b * NN + n) * THC;
    const int col = h * DH + pair * 2;

    float2 qv = *(const float2*)&src[col];
    float2 kv = *(const float2*)&src[HIDDEN + col];
    float2 vv = *(const float2*)&src[2 * HIDDEN + col];

    float fr = (float)n * c_invfreq[pair];
    float sn, cs;
    sincosf(fr, &sn, &cs);

    const float scale = 0.125f;
    float oq0 = (qv.x * cs - qv.y * sn) * scale;
    float oq1 = (qv.y * cs + qv.x * sn) * scale;
    float ok0 = kv.x * cs - kv.y * sn;
    float ok1 = kv.y * cs + kv.x * sn;

    size_t o = ((size_t)bh * NN + n) * DH + pair * 2;
    g_q[o] = oq0; g_q[o + 1] = oq1;
    g_k[o] = ok0; g_k[o + 1] = ok1;
    g_v[o] = vv.x; g_v[o + 1] = vv.y;
}

// =====================================================================
// Fused flash attention, tf32 tensor cores, cp.async pipelined.
// (unchanged from R8 — measured component ~285us)
// =====================================================================
#define TSTRIDE 656
#define SSTRIDE 68
#define STG_CHUNK (32 * SSTRIDE)

__global__ __launch_bounds__(256, 2)
void attn_tf32(const float* __restrict__ bias)
{
    extern __shared__ unsigned smem_u[];
    unsigned* KF  = smem_u;                      // [2][4*TSTRIDE]
    unsigned* VF  = smem_u + 2 * 4 * TSTRIDE;    // [2][4*TSTRIDE]
    float*    stK = (float*)(smem_u + 4 * 4 * TSTRIDE);  // [2][32*68]
    float*    stV = stK + 2 * STG_CHUNK;                  // [2][32*68]

    const int tid  = threadIdx.x;
    const int lane = tid & 31;
    const int w    = tid >> 5;
    const int qg   = lane >> 2;
    const int q    = lane & 3;
    const int qblk = blockIdx.x * 128;
    const int h    = blockIdx.y;
    const int b    = blockIdx.z;
    const size_t base = ((size_t)(b * HEADS + h)) * NN * DH;
    const float* gk = g_k + base;
    const float* gv = g_v + base;
    const float* biasw = bias + (size_t)h * NN * NN
                              + (size_t)(qblk + w * 16) * NN;

    const int wr  = tid >> 3;
    const int wc8 = (tid & 7) * 8;
    const int wt  = wr >> 3;
    const int wqg = wr & 7;
    const int wq  = wr & 3;
    const int whf = (wr >> 2) & 1;
    const int wkc = tid & 7;
    const int kdst = wt * TSTRIDE + wqg * 80 + (wqg >= 4 ? 8 : 0) + wkc * 2;
    const int vdst = wt * TSTRIDE + wq * 20 + wkc * 2 + whf;
    const int stoff = wr * SSTRIDE + wc8;
    const int rb = lane * 20 + (lane >= 16 ? 8 : 0);

    unsigned qa[8][4];
    {
        const float* Qp = g_q + base + (size_t)(qblk + w * 16) * DH;
#pragma unroll
        for (int kc = 0; kc < 8; ++kc) {
            qa[kc][0] = cvt_tf32(Qp[(size_t)qg       * DH + kc * 8 + q]);
            qa[kc][1] = cvt_tf32(Qp[(size_t)(qg + 8) * DH + kc * 8 + q]);
            qa[kc][2] = cvt_tf32(Qp[(size_t)qg       * DH + kc * 8 + q + 4]);
            qa[kc][3] = cvt_tf32(Qp[(size_t)(qg + 8) * DH + kc * 8 + q + 4]);
        }
    }

    cp16(&stK[stoff], gk + (size_t)wr * DH + wc8);
    cp16(&stK[stoff + 4], gk + (size_t)wr * DH + wc8 + 4);
    cp16(&stV[stoff], gv + (size_t)wr * DH + wc8);
    cp16(&stV[stoff + 4], gv + (size_t)wr * DH + wc8 + 4);
    cp_commit();
    cp16(&stK[STG_CHUNK + stoff], gk + (size_t)(32 + wr) * DH + wc8);
    cp16(&stK[STG_CHUNK + stoff + 4], gk + (size_t)(32 + wr) * DH + wc8 + 4);
    cp16(&stV[STG_CHUNK + stoff], gv + (size_t)(32 + wr) * DH + wc8);
    cp16(&stV[STG_CHUNK + stoff + 4], gv + (size_t)(32 + wr) * DH + wc8 + 4);
    cp_commit();

    float S[4][4];
    cp_wait1();
    {
#pragma unroll
        for (int t = 0; t < 4; ++t) {
            float2 blo = *(const float2*)&biasw[(size_t)qg       * NN + t * 8 + 2 * q];
            float2 bhi = *(const float2*)&biasw[(size_t)(qg + 8) * NN + t * 8 + 2 * q];
            S[t][0] = blo.x; S[t][1] = blo.y;
            S[t][2] = bhi.x; S[t][3] = bhi.y;
        }
        float4 k0 = *(const float4*)&stK[stoff];
        float4 k1 = *(const float4*)&stK[stoff + 4];
        float4 v0 = *(const float4*)&stV[stoff];
        float4 v1 = *(const float4*)&stV[stoff + 4];
        unsigned* kf = KF;
        unsigned* vf = VF;
        kf[kdst +  0] = cvt_tf32(k0.x); kf[kdst + 20] = cvt_tf32(k0.y);
        kf[kdst + 40] = cvt_tf32(k0.z); kf[kdst + 60] = cvt_tf32(k0.w);
        kf[kdst +  1] = cvt_tf32(k1.x); kf[kdst + 21] = cvt_tf32(k1.y);
        kf[kdst + 41] = cvt_tf32(k1.z); kf[kdst + 61] = cvt_tf32(k1.w);
        vf[vdst +   0]     = cvt_tf32(v0.x);
        vf[vdst +  80]     = cvt_tf32(v0.y);
        vf[vdst + 160]     = cvt_tf32(v0.z);
        vf[vdst + 240]     = cvt_tf32(v0.w);
        vf[vdst + 320 + 8] = cvt_tf32(v1.x);
        vf[vdst + 400 + 8] = cvt_tf32(v1.y);
        vf[vdst + 480 + 8] = cvt_tf32(v1.z);
        vf[vdst + 560 + 8] = cvt_tf32(v1.w);
    }
    __syncthreads();

    float O[8][4];
#pragma unroll
    for (int n = 0; n < 8; ++n)
#pragma unroll
        for (int j = 0; j < 4; ++j) O[n][j] = 0.f;
    float m0 = -INFINITY, m1 = -INFINITY, l0 = 0.f, l1 = 0.f;

    for (int j = 0; j < 64; ++j) {
        const int p = j & 1;

        const unsigned* kfp = KF + p * (4 * TSTRIDE);
#pragma unroll
        for (int t = 0; t < 4; ++t) {
            const uint4* kk = (const uint4*)&kfp[t * TSTRIDE + rb];
            uint4 k0 = kk[0], k1 = kk[1], k2 = kk[2], k3 = kk[3];
            mma_tf32(S[t], qa[0][0], qa[0][1], qa[0][2], qa[0][3], k0.x, k0.y);
            mma_tf32(S[t], qa[1][0], qa[1][1], qa[1][2], qa[1][3], k0.z, k0.w);
            mma_tf32(S[t], qa[2][0], qa[2][1], qa[2][2], qa[2][3], k1.x, k1.y);
            mma_tf32(S[t], qa[3][0], qa[3][1], qa[3][2], qa[3][3], k1.z, k1.w);
            mma_tf32(S[t], qa[4][0], qa[4][1], qa[4][2], qa[4][3], k2.x, k2.y);
            mma_tf32(S[t], qa[5][0], qa[5][1], qa[5][2], qa[5][3], k2.z, k2.w);
            mma_tf32(S[t], qa[6][0], qa[6][1], qa[6][2], qa[6][3], k3.x, k3.y);
            mma_tf32(S[t], qa[7][0], qa[7][1], qa[7][2], qa[7][3], k3.z, k3.w);
        }

        float cm0 = -INFINITY, cm1 = -INFINITY;
#pragma unroll
        for (int t = 0; t < 4; ++t) {
            cm0 = fmaxf(cm0, fmaxf(S[t][0], S[t][1]));
            cm1 = fmaxf(cm1, fmaxf(S[t][2], S[t][3]));
        }
        cm0 = fmaxf(cm0, __shfl_xor_sync(0xffffffffu, cm0, 1));
        cm0 = fmaxf(cm0, __shfl_xor_sync(0xffffffffu, cm0, 2));
        cm1 = fmaxf(cm1, __shfl_xor_sync(0xffffffffu, cm1, 1));
        cm1 = fmaxf(cm1, __shfl_xor_sync(0xffffffffu, cm1, 2));

        float mn0 = fmaxf(m0, cm0), mn1 = fmaxf(m1, cm1);
        float al0 = __expf(m0 - mn0), al1 = __expf(m1 - mn1);
        m0 = mn0; m1 = mn1;

        float s0 = 0.f, s1 = 0.f;
#pragma unroll
        for (int t = 0; t < 4; ++t) {
            S[t][0] = __expf(S[t][0] - mn0);
            S[t][1] = __expf(S[t][1] - mn0);
            S[t][2] = __expf(S[t][2] - mn1);
            S[t][3] = __expf(S[t][3] - mn1);
            s0 += S[t][0] + S[t][1];
            s1 += S[t][2] + S[t][3];
        }
        s0 += __shfl_xor_sync(0xffffffffu, s0, 1);
        s0 += __shfl_xor_sync(0xffffffffu, s0, 2);
        s1 += __shfl_xor_sync(0xffffffffu, s1, 1);
        s1 += __shfl_xor_sync(0xffffffffu, s1, 2);
        l0 = l0 * al0 + s0;
        l1 = l1 * al1 + s1;
#pragma unroll
        for (int n = 0; n < 8; ++n) {
            O[n][0] *= al0; O[n][1] *= al0;
            O[n][2] *= al1; O[n][3] *= al1;
        }

        const unsigned* vfp = VF + p * (4 * TSTRIDE);
        const int srcA = (lane & ~3) | (q >> 1);
        const int srcB = srcA | 2;
#pragma unroll
        for (int t = 0; t < 4; ++t) {
            unsigned p0 = cvt_tf32(S[t][0]);
            unsigned p1 = cvt_tf32(S[t][1]);
            unsigned p2 = cvt_tf32(S[t][2]);
            unsigned p3 = cvt_tf32(S[t][3]);
            unsigned u0 = __shfl_sync(0xffffffffu, p0, srcA);
            unsigned u1 = __shfl_sync(0xffffffffu, p1, srcA);
            unsigned v0s = __shfl_sync(0xffffffffu, p0, srcB);
            unsigned v1s = __shfl_sync(0xffffffffu, p1, srcB);
            unsigned w0 = __shfl_sync(0xffffffffu, p2, srcA);
            unsigned w1 = __shfl_sync(0xffffffffu, p3, srcA);
            unsigned x0 = __shfl_sync(0xffffffffu, p2, srcB);
            unsigned x1 = __shfl_sync(0xffffffffu, p3, srcB);
            unsigned a0 = (q & 1) ? u1 : u0;
            unsigned a1 = (q & 1) ? w1 : w0;
            unsigned a2 = (q & 1) ? v1s : v0s;
            unsigned a3 = (q & 1) ? x1 : x0;
            const uint4* vv = (const uint4*)&vfp[t * TSTRIDE + rb];
            uint4 v0 = vv[0], v1 = vv[1], v2 = vv[2], v3 = vv[3];
            mma_tf32(O[0], a0, a1, a2, a3, v0.x, v0.y);
            mma_tf32(O[1], a0, a1, a2, a3, v0.z, v0.w);
            mma_tf32(O[2], a0, a1, a2, a3, v1.x, v1.y);
            mma_tf32(O[3], a0, a1, a2, a3, v1.z, v1.w);
            mma_tf32(O[4], a0, a1, a2, a3, v2.x, v2.y);
            mma_tf32(O[5], a0, a1, a2, a3, v2.z, v2.w);
            mma_tf32(O[6], a0, a1, a2, a3, v3.x, v3.y);
            mma_tf32(O[7], a0, a1, a2, a3, v3.z, v3.w);
        }

        {
            const int jc = (j + 2 < 64) ? j + 2 : 63;
            const size_t roff = (size_t)(jc * 32 + wr) * DH + wc8;
            float* sk = &stK[p * STG_CHUNK + stoff];
            float* sv = &stV[p * STG_CHUNK + stoff];
            cp16(sk,     gk + roff);
            cp16(sk + 4, gk + roff + 4);
            cp16(sv,     gv + roff);
            cp16(sv + 4, gv + roff + 4);
            cp_commit();
        }
        cp_wait1();

        {
            const int jb = (j + 1 < 64) ? j + 1 : 63;
            const int j0n = jb * 32;
#pragma unroll
            for (int t = 0; t < 4; ++t) {
                float2 blo = *(const float2*)
                    &biasw[(size_t)qg       * NN + j0n + t * 8 + 2 * q];
                float2 bhi = *(const float2*)
                    &biasw[(size_t)(qg + 8) * NN + j0n + t * 8 + 2 * q];
                S[t][0] = blo.x; S[t][1] = blo.y;
                S[t][2] = bhi.x; S[t][3] = bhi.y;
            }
        }

        {
            const int pn = p ^ 1;
            const float* sk = &stK[pn * STG_CHUNK + stoff];
            const float* sv = &stV[pn * STG_CHUNK + stoff];
            float4 k0 = *(const float4*)sk;
            float4 k1 = *(const float4*)(sk + 4);
            float4 v0 = *(const float4*)sv;
            float4 v1 = *(const float4*)(sv + 4);
            unsigned* kf = KF + pn * (4 * TSTRIDE);
            unsigned* vf = VF + pn * (4 * TSTRIDE);
            kf[kdst +  0] = cvt_tf32(k0.x); kf[kdst + 20] = cvt_tf32(k0.y);
            kf[kdst + 40] = cvt_tf32(k0.z); kf[kdst + 60] = cvt_tf32(k0.w);
            kf[kdst +  1] = cvt_tf32(k1.x); kf[kdst + 21] = cvt_tf32(k1.y);
            kf[kdst + 41] = cvt_tf32(k1.z); kf[kdst + 61] = cvt_tf32(k1.w);
            vf[vdst +   0]     = cvt_tf32(v0.x);
            vf[vdst +  80]     = cvt_tf32(v0.y);
            vf[vdst + 160]     = cvt_tf32(v0.z);
            vf[vdst + 240]     = cvt_tf32(v0.w);
            vf[vdst + 320 + 8] = cvt_tf32(v1.x);
            vf[vdst + 400 + 8] = cvt_tf32(v1.y);
            vf[vdst + 480 + 8] = cvt_tf32(v1.z);
            vf[vdst + 560 + 8] = cvt_tf32(v1.w);
        }
        __syncthreads();
    }

    const float il0 = 1.f / l0, il1 = 1.f / l1;
    const int row0 = qblk + w * 16 + qg;
    const int row1 = row0 + 8;
#pragma unroll
    for (int n = 0; n < 8; ++n) {
        float2 olo = make_float2(O[n][0] * il0, O[n][1] * il0);
        float2 ohi = make_float2(O[n][2] * il1, O[n][3] * il1);
        *(float2*)&g_mid[(size_t)(b * NN + row0) * HIDDEN
                         + h * DH + n * 8 + 2 * q] = olo;
        *(float2*)&g_mid[(size_t)(b * NN + row1) * HIDDEN
                         + h * DH + n * 8 + 2 * q] = ohi;
    }
}

#define ATTN_SMEM (4 * (4 * 4 * TSTRIDE + 4 * STG_CHUNK))

// =====================================================================
extern "C" void kernel_launch(void* const* d_in, const int* in_sizes, int n_in,
                              void* d_out, int out_size)
{
    const float *x = nullptr, *bias = nullptr, *wqkv = nullptr, *wout = nullptr;
    for (int i = 0; i < n_in; ++i) {
        switch (in_sizes[i]) {
            case 4194304:  x    = (const float*)d_in[i]; break;  // x [4,2048,512]
            case 33554432: bias = (const float*)d_in[i]; break;  // pos_bias [8,2048,2048]
            case 786432:   wqkv = (const float*)d_in[i]; break;  // W_qkv [512,1536]
            case 262144:   wout = (const float*)d_in[i]; break;  // W_out [512,512]
        }
    }

    void *p_qkv = nullptr, *p_mid = nullptr;
    cudaGetSymbolAddress(&p_qkv, g_qkv);
    cudaGetSymbolAddress(&p_mid, g_mid);

    // opt-in to >48KB dynamic smem (non-stream calls: capture-safe)
    cudaFuncSetAttribute(attn_tf32,
                         cudaFuncAttributeMaxDynamicSharedMemorySize,
                         ATTN_SMEM);
    cudaFuncSetAttribute(mma_gemm1x,
                         cudaFuncAttributeMaxDynamicSharedMemorySize,
                         GEMM_SMEM_1X);

    // 1) qkv = x @ W_qkv  (fp32-exact FFMA2, cp.async double-buffered)
    sgemm128<<<dim3(THC / 64, (BB * NN) / 128), 256>>>(
        x, wqkv, (float*)p_qkv, BB * NN, THC, DIM);

    // 2) split + rotary + scale
    qkv_transform<<<(BB * HEADS * NN * 32) / 256, 256>>>();

    // 3) fused flash attention (tf32 tensor cores, cp.async pipelined)
    attn_tf32<<<dim3(NN / 128, HEADS, BB), 256, ATTN_SMEM>>>(bias);

    // 4) out = mid @ W_out  (1x tf32 mma; terminal, measured error budget)
    mma_gemm1x<<<dim3(DIM / 64, (BB * NN) / 128), 256, GEMM_SMEM_1X>>>(
        (const float*)p_mid, wout, (float*)d_out, BB * NN, DIM, HIDDEN);
}

// round 11
// speedup vs baseline: 1.4179x; 1.2618x over previous
#include <cuda_runtime.h>
#include <math.h>

// Problem constants
#define BB 4
#define NN 2048
#define DIM 512
#define HEADS 8
#define DH 64
#define HIDDEN 512          // HEADS*DH
#define THC 1536            // 3*HIDDEN

// ---------------- scratch (device globals: allocation-free rule) ----------
__device__ float    g_qkv[(size_t)BB * NN * THC];          // 48 MB
__device__ float    g_q  [(size_t)BB * HEADS * NN * DH];   // 16 MB
__device__ float    g_k  [(size_t)BB * HEADS * NN * DH];   // 16 MB
__device__ float    g_v  [(size_t)BB * HEADS * NN * DH];   // 16 MB
__device__ float    g_mid[(size_t)BB * NN * HIDDEN];       // 16 MB
// fragment-major packed operands (tf32 bit patterns)
__device__ unsigned g_xp  [(size_t)BB * NN * DIM];         // 16 MB  x packed
__device__ unsigned g_wq_hi[(size_t)DIM * THC];            // 3 MB
__device__ unsigned g_wq_lo[(size_t)DIM * THC];            // 3 MB
__device__ unsigned g_mp  [(size_t)BB * NN * HIDDEN];      // 16 MB  mid packed
__device__ unsigned g_wo_hi[(size_t)HIDDEN * DIM];         // 1 MB

// inv_freq[i] = 10000^(-2i/64) = 10^(-i/8), correctly-rounded fp32
__constant__ float c_invfreq[32] = {
    1.0f,
    0.74989420933245582f, 0.56234132519034907f, 0.42169650342858220f,
    0.31622776601683794f, 0.23713737056616552f, 0.17782794100389228f,
    0.13335214321633240f, 0.1f,
    0.074989420933245582f, 0.056234132519034907f, 0.042169650342858220f,
    0.031622776601683794f, 0.023713737056616552f, 0.017782794100389228f,
    0.013335214321633240f, 0.01f,
    0.0074989420933245582f, 0.0056234132519034907f, 0.0042169650342858220f,
    0.0031622776601683794f, 0.0023713737056616552f, 0.0017782794100389228f,
    0.0013335214321633240f, 0.001f,
    0.00074989420933245582f, 0.00056234132519034907f, 0.00042169650342858220f,
    0.00031622776601683794f, 0.00023713737056616552f, 0.00017782794100389228f,
    0.00013335214321633240f
};

// ---------------- tf32 helpers ----------------
__device__ __forceinline__ unsigned cvt_tf32(float f) {
    unsigned r;
    asm("cvt.rna.tf32.f32 %0, %1;" : "=r"(r) : "f"(f));
    return r;
}

__device__ __forceinline__ void mma_tf32(float c[4],
                                         unsigned a0, unsigned a1,
                                         unsigned a2, unsigned a3,
                                         unsigned b0, unsigned b1) {
    asm volatile(
        "mma.sync.aligned.m16n8k8.row.col.f32.tf32.tf32.f32 "
        "{%0,%1,%2,%3}, {%4,%5,%6,%7}, {%8,%9}, {%0,%1,%2,%3};\n"
        : "+f"(c[0]), "+f"(c[1]), "+f"(c[2]), "+f"(c[3])
        : "r"(a0), "r"(a1), "r"(a2), "r"(a3), "r"(b0), "r"(b1));
}

__device__ __forceinline__ void cp16(void* dst_smem, const void* src_gmem) {
    unsigned s = (unsigned)__cvta_generic_to_shared(dst_smem);
    asm volatile("cp.async.cg.shared.global [%0], [%1], 16;"
                 :: "r"(s), "l"(src_gmem));
}
__device__ __forceinline__ void cp_commit() {
    asm volatile("cp.async.commit_group;");
}
__device__ __forceinline__ void cp_wait1() {
    asm volatile("cp.async.wait_group 1;");
}

// =====================================================================
// Pack kernels: rewrite matrices into m16n8k8 fragment-major tf32 layout.
// A layout [M/16][K/8][128]: word[lane*4+r] = a_r of lane (qg=lane>>2,q=lane&3)
//   a0=(qg, q)  a1=(qg+8, q)  a2=(qg, q+4)  a3=(qg+8, q+4)
// B layout [N/8][K/16][128]: word[lane*4+r]:
//   r0=(k=q, n=qg)  r1=(k=q+4, n=qg)  r2=(k=8+q, n=qg)  r3=(k=12+q, n=qg)
// (identical fragment mappings to the proven attention kernel)
// =====================================================================
__global__ __launch_bounds__(256)
void pack_a(const float* __restrict__ src, unsigned* __restrict__ dst, int K)
{
    const int gw   = (blockIdx.x * 256 + threadIdx.x) >> 5;
    const int lane = threadIdx.x & 31;
    const int KB   = K >> 3;
    const int mb   = gw / KB;
    const int kb   = gw - mb * KB;
    const int qg   = lane >> 2, q = lane & 3;
    const float* s = src + (size_t)(mb * 16 + qg) * K + kb * 8 + q;
    uint4 o;
    o.x = cvt_tf32(s[0]);
    o.y = cvt_tf32(s[(size_t)8 * K]);
    o.z = cvt_tf32(s[4]);
    o.w = cvt_tf32(s[(size_t)8 * K + 4]);
    *(uint4*)&dst[(size_t)gw * 128 + lane * 4] = o;
}

__global__ __launch_bounds__(256)
void pack_b(const float* __restrict__ src, unsigned* __restrict__ hi,
            unsigned* __restrict__ lo, int K, int N)
{
    const int gw   = (blockIdx.x * 256 + threadIdx.x) >> 5;
    const int lane = threadIdx.x & 31;
    const int KB2  = K >> 4;
    const int nb   = gw / KB2;
    const int kb2  = gw - nb * KB2;
    const int qg   = lane >> 2, q = lane & 3;
    const float* s = src + (size_t)(kb2 * 16 + q) * N + nb * 8 + qg;
    float v0 = s[0], v1 = s[(size_t)4 * N], v2 = s[(size_t)8 * N],
          v3 = s[(size_t)12 * N];
    uint4 h;
    h.x = cvt_tf32(v0); h.y = cvt_tf32(v1);
    h.z = cvt_tf32(v2); h.w = cvt_tf32(v3);
    *(uint4*)&hi[(size_t)gw * 128 + lane * 4] = h;
    if (lo) {
        uint4 l;
        l.x = cvt_tf32(v0 - __uint_as_float(h.x));
        l.y = cvt_tf32(v1 - __uint_as_float(h.y));
        l.z = cvt_tf32(v2 - __uint_as_float(h.z));
        l.w = cvt_tf32(v3 - __uint_as_float(h.w));
        *(uint4*)&lo[(size_t)gw * 128 + lane * 4] = l;
    }
}

// =====================================================================
// Packed tensor-core GEMM: C[M,Nc] = A @ B, operands pre-packed tf32.
// PB = number of B planes (1: hi only; 2: hi+lo exact-weight split).
// Block 128m x 64n, 256 threads (8 warps; warp w owns rows w*16..w*16+15).
// K-step 32. 3-stage cp.async pipeline, ONE barrier per iter:
//   iter it: issue tile(it+2)->buf[(it+2)%3] | compute buf[it%3] |
//            wait_group(1) (own tile(it+1) copies done) | __syncthreads.
// Hot loop: LDS.128 frag loads + mma only (no cvt, no scatter).
// =====================================================================
#define ABUF 4096   // words per A buffer (8 mb x 4 kk x 128)
#define BBUF 2048   // words per B-plane buffer (8 nb x 2 kb2 x 128)

template<int PB>
__global__ __launch_bounds__(256)
void pgemm(const unsigned* __restrict__ Ap, const unsigned* __restrict__ Bh,
           const unsigned* __restrict__ Bl, float* __restrict__ C,
           int M, int Nc, int K)
{
    extern __shared__ unsigned sm[];
    unsigned* As  = sm;                    // [3][ABUF]
    unsigned* Bhs = sm + 3 * ABUF;         // [3][BBUF]
    unsigned* Bls = sm + 3 * ABUF + 3 * BBUF;  // [3][BBUF] (PB==2)

    const int tid  = threadIdx.x;
    const int lane = tid & 31;
    const int w    = tid >> 5;
    const int qg   = lane >> 2;
    const int q    = lane & 3;
    const int m0   = blockIdx.y * 128;
    const int n0   = blockIdx.x * 64;
    const int KB   = K >> 3;
    const int KB2  = K >> 4;
    const int NK   = K >> 5;

    const unsigned* Ag  = Ap + (size_t)(m0 >> 4) * KB * 128;
    const unsigned* Bhg = Bh + (size_t)(n0 >> 3) * KB2 * 128;
    const unsigned* Blg = (PB == 2) ? Bl + (size_t)(n0 >> 3) * KB2 * 128
                                    : (const unsigned*)0;

    const int cw  = tid >> 5;         // copy chunk (mb / nb local)
    const int lw4 = (tid & 31) * 4;

    auto issue_tile = [&](int it, int p) {
        // A: warp chunk = mb local cw; 4 consecutive kb blocks contiguous
        const unsigned* ga = Ag + ((size_t)cw * KB + it * 4) * 128;
        unsigned* da = As + p * ABUF + cw * 512;
#pragma unroll
        for (int s = 0; s < 4; ++s)
            cp16(da + s * 128 + lw4, ga + s * 128 + lw4);
        // B hi: nb local cw; 2 consecutive kb2 blocks contiguous
        const unsigned* gb = Bhg + ((size_t)cw * KB2 + it * 2) * 128;
        unsigned* db = Bhs + p * BBUF + cw * 256;
#pragma unroll
        for (int s = 0; s < 2; ++s)
            cp16(db + s * 128 + lw4, gb + s * 128 + lw4);
        if (PB == 2) {
            const unsigned* gl = Blg + ((size_t)cw * KB2 + it * 2) * 128;
            unsigned* dl = Bls + p * BBUF + cw * 256;
#pragma unroll
            for (int s = 0; s < 2; ++s)
                cp16(dl + s * 128 + lw4, gl + s * 128 + lw4);
        }
        cp_commit();
    };

    float C_[8][4];
#pragma unroll
    for (int nt = 0; nt < 8; ++nt)
#pragma unroll
        for (int j = 0; j < 4; ++j) C_[nt][j] = 0.f;

    // prologue: tiles 0 and 1 in flight
    issue_tile(0, 0);
    issue_tile(1, 1);
    cp_wait1();        // own tile-0 copies done
    __syncthreads();   // everyone's tile-0 copies done

    for (int it = 0; it < NK; ++it) {
        const int p = it % 3;

        // issue tile it+2 into the buffer freed at end of iter it-1
        const int itn = (it + 2 < NK) ? it + 2 : NK - 1;
        issue_tile(itn, (it + 2) % 3);

        // ---- compute tile it ----
        uint4 af[4];
#pragma unroll
        for (int kk = 0; kk < 4; ++kk)
            af[kk] = *(const uint4*)&As[p * ABUF + w * 512 + kk * 128 + lane * 4];
#pragma unroll
        for (int nt = 0; nt < 8; ++nt) {
            const unsigned* bb = &Bhs[p * BBUF + nt * 256 + lane * 4];
            uint4 b0 = *(const uint4*)bb;
            uint4 b1 = *(const uint4*)(bb + 128);
            mma_tf32(C_[nt], af[0].x, af[0].y, af[0].z, af[0].w, b0.x, b0.y);
            mma_tf32(C_[nt], af[1].x, af[1].y, af[1].z, af[1].w, b0.z, b0.w);
            mma_tf32(C_[nt], af[2].x, af[2].y, af[2].z, af[2].w, b1.x, b1.y);
            mma_tf32(C_[nt], af[3].x, af[3].y, af[3].z, af[3].w, b1.z, b1.w);
            if (PB == 2) {
                const unsigned* bl = &Bls[p * BBUF + nt * 256 + lane * 4];
                uint4 l0 = *(const uint4*)bl;
                uint4 l1 = *(const uint4*)(bl + 128);
                mma_tf32(C_[nt], af[0].x, af[0].y, af[0].z, af[0].w, l0.x, l0.y);
                mma_tf32(C_[nt], af[1].x, af[1].y, af[1].z, af[1].w, l0.z, l0.w);
                mma_tf32(C_[nt], af[2].x, af[2].y, af[2].z, af[2].w, l1.x, l1.y);
                mma_tf32(C_[nt], af[3].x, af[3].y, af[3].z, af[3].w, l1.z, l1.w);
            }
        }

        cp_wait1();        // own tile(it+1) copies complete
        __syncthreads();   // publish tile(it+1); buffer (it)%3 free for reuse
    }

    // ---- epilogue ----
#pragma unroll
    for (int nt = 0; nt < 8; ++nt) {
        int col = n0 + nt * 8 + 2 * q;
        size_t row = (size_t)(m0 + w * 16 + qg);
        *(float2*)&C[row * Nc + col]       = make_float2(C_[nt][0], C_[nt][1]);
        *(float2*)&C[(row + 8) * Nc + col] = make_float2(C_[nt][2], C_[nt][3]);
    }
}

#define PGEMM_SMEM_2 (4 * (3 * ABUF + 3 * BBUF * 2))   // 98304 B
#define PGEMM_SMEM_1 (4 * (3 * ABUF + 3 * BBUF))       // 73728 B

// =====================================================================
// QKV split + head reshape + rotary (+ q scale).
// =====================================================================
__global__ __launch_bounds__(256)
void qkv_transform()
{
    const int idx  = blockIdx.x * 256 + threadIdx.x;
    const int pair = idx & 31;
    const int n    = (idx >> 5) & (NN - 1);
    const int bh   = idx >> 16;
    const int b    = bh >> 3;
    const int h    = bh & 7;

    const float* src = g_qkv + (size_t)(b * NN + n) * THC;
    const int col = h * DH + pair * 2;

    float2 qv = *(const float2*)&src[col];
    float2 kv = *(const float2*)&src[HIDDEN + col];
    float2 vv = *(const float2*)&src[2 * HIDDEN + col];

    float fr = (float)n * c_invfreq[pair];
    float sn, cs;
    sincosf(fr, &sn, &cs);

    const float scale = 0.125f;
    float oq0 = (qv.x * cs - qv.y * sn) * scale;
    float oq1 = (qv.y * cs + qv.x * sn) * scale;
    float ok0 = kv.x * cs - kv.y * sn;
    float ok1 = kv.y * cs + kv.x * sn;

    size_t o = ((size_t)bh * NN + n) * DH + pair * 2;
    g_q[o] = oq0; g_q[o + 1] = oq1;
    g_k[o] = ok0; g_k[o + 1] = ok1;
    g_v[o] = vv.x; g_v[o + 1] = vv.y;
}

// =====================================================================
// Fused flash attention, tf32 tensor cores, cp.async pipelined.
// (unchanged — measured component ~285us)
// =====================================================================
#define TSTRIDE 656
#define SSTRIDE 68
#define STG_CHUNK (32 * SSTRIDE)

__global__ __launch_bounds__(256, 2)
void attn_tf32(const float* __restrict__ bias)
{
    extern __shared__ unsigned smem_u[];
    unsigned* KF  = smem_u;                      // [2][4*TSTRIDE]
    unsigned* VF  = smem_u + 2 * 4 * TSTRIDE;    // [2][4*TSTRIDE]
    float*    stK = (float*)(smem_u + 4 * 4 * TSTRIDE);  // [2][32*68]
    float*    stV = stK + 2 * STG_CHUNK;                  // [2][32*68]

    const int tid  = threadIdx.x;
    const int lane = tid & 31;
    const int w    = tid >> 5;
    const int qg   = lane >> 2;
    const int q    = lane & 3;
    const int qblk = blockIdx.x * 128;
    const int h    = blockIdx.y;
    const int b    = blockIdx.z;
    const size_t base = ((size_t)(b * HEADS + h)) * NN * DH;
    const float* gk = g_k + base;
    const float* gv = g_v + base;
    const float* biasw = bias + (size_t)h * NN * NN
                              + (size_t)(qblk + w * 16) * NN;

    const int wr  = tid >> 3;
    const int wc8 = (tid & 7) * 8;
    const int wt  = wr >> 3;
    const int wqg = wr & 7;
    const int wq  = wr & 3;
    const int whf = (wr >> 2) & 1;
    const int wkc = tid & 7;
    const int kdst = wt * TSTRIDE + wqg * 80 + (wqg >= 4 ? 8 : 0) + wkc * 2;
    const int vdst = wt * TSTRIDE + wq * 20 + wkc * 2 + whf;
    const int stoff = wr * SSTRIDE + wc8;
    const int rb = lane * 20 + (lane >= 16 ? 8 : 0);

    unsigned qa[8][4];
    {
        const float* Qp = g_q + base + (size_t)(qblk + w * 16) * DH;
#pragma unroll
        for (int kc = 0; kc < 8; ++kc) {
            qa[kc][0] = cvt_tf32(Qp[(size_t)qg       * DH + kc * 8 + q]);
            qa[kc][1] = cvt_tf32(Qp[(size_t)(qg + 8) * DH + kc * 8 + q]);
            qa[kc][2] = cvt_tf32(Qp[(size_t)qg       * DH + kc * 8 + q + 4]);
            qa[kc][3] = cvt_tf32(Qp[(size_t)(qg + 8) * DH + kc * 8 + q + 4]);
        }
    }

    cp16(&stK[stoff], gk + (size_t)wr * DH + wc8);
    cp16(&stK[stoff + 4], gk + (size_t)wr * DH + wc8 + 4);
    cp16(&stV[stoff], gv + (size_t)wr * DH + wc8);
    cp16(&stV[stoff + 4], gv + (size_t)wr * DH + wc8 + 4);
    cp_commit();
    cp16(&stK[STG_CHUNK + stoff], gk + (size_t)(32 + wr) * DH + wc8);
    cp16(&stK[STG_CHUNK + stoff + 4], gk + (size_t)(32 + wr) * DH + wc8 + 4);
    cp16(&stV[STG_CHUNK + stoff], gv + (size_t)(32 + wr) * DH + wc8);
    cp16(&stV[STG_CHUNK + stoff + 4], gv + (size_t)(32 + wr) * DH + wc8 + 4);
    cp_commit();

    float S[4][4];
    cp_wait1();
    {
#pragma unroll
        for (int t = 0; t < 4; ++t) {
            float2 blo = *(const float2*)&biasw[(size_t)qg       * NN + t * 8 + 2 * q];
            float2 bhi = *(const float2*)&biasw[(size_t)(qg + 8) * NN + t * 8 + 2 * q];
            S[t][0] = blo.x; S[t][1] = blo.y;
            S[t][2] = bhi.x; S[t][3] = bhi.y;
        }
        float4 k0 = *(const float4*)&stK[stoff];
        float4 k1 = *(const float4*)&stK[stoff + 4];
        float4 v0 = *(const float4*)&stV[stoff];
        float4 v1 = *(const float4*)&stV[stoff + 4];
        unsigned* kf = KF;
        unsigned* vf = VF;
        kf[kdst +  0] = cvt_tf32(k0.x); kf[kdst + 20] = cvt_tf32(k0.y);
        kf[kdst + 40] = cvt_tf32(k0.z); kf[kdst + 60] = cvt_tf32(k0.w);
        kf[kdst +  1] = cvt_tf32(k1.x); kf[kdst + 21] = cvt_tf32(k1.y);
        kf[kdst + 41] = cvt_tf32(k1.z); kf[kdst + 61] = cvt_tf32(k1.w);
        vf[vdst +   0]     = cvt_tf32(v0.x);
        vf[vdst +  80]     = cvt_tf32(v0.y);
        vf[vdst + 160]     = cvt_tf32(v0.z);
        vf[vdst + 240]     = cvt_tf32(v0.w);
        vf[vdst + 320 + 8] = cvt_tf32(v1.x);
        vf[vdst + 400 + 8] = cvt_tf32(v1.y);
        vf[vdst + 480 + 8] = cvt_tf32(v1.z);
        vf[vdst + 560 + 8] = cvt_tf32(v1.w);
    }
    __syncthreads();

    float O[8][4];
#pragma unroll
    for (int n = 0; n < 8; ++n)
#pragma unroll
        for (int j = 0; j < 4; ++j) O[n][j] = 0.f;
    float m0 = -INFINITY, m1 = -INFINITY, l0 = 0.f, l1 = 0.f;

    for (int j = 0; j < 64; ++j) {
        const int p = j & 1;

        const unsigned* kfp = KF + p * (4 * TSTRIDE);
#pragma unroll
        for (int t = 0; t < 4; ++t) {
            const uint4* kk = (const uint4*)&kfp[t * TSTRIDE + rb];
            uint4 k0 = kk[0], k1 = kk[1], k2 = kk[2], k3 = kk[3];
            mma_tf32(S[t], qa[0][0], qa[0][1], qa[0][2], qa[0][3], k0.x, k0.y);
            mma_tf32(S[t], qa[1][0], qa[1][1], qa[1][2], qa[1][3], k0.z, k0.w);
            mma_tf32(S[t], qa[2][0], qa[2][1], qa[2][2], qa[2][3], k1.x, k1.y);
            mma_tf32(S[t], qa[3][0], qa[3][1], qa[3][2], qa[3][3], k1.z, k1.w);
            mma_tf32(S[t], qa[4][0], qa[4][1], qa[4][2], qa[4][3], k2.x, k2.y);
            mma_tf32(S[t], qa[5][0], qa[5][1], qa[5][2], qa[5][3], k2.z, k2.w);
            mma_tf32(S[t], qa[6][0], qa[6][1], qa[6][2], qa[6][3], k3.x, k3.y);
            mma_tf32(S[t], qa[7][0], qa[7][1], qa[7][2], qa[7][3], k3.z, k3.w);
        }

        float cm0 = -INFINITY, cm1 = -INFINITY;
#pragma unroll
        for (int t = 0; t < 4; ++t) {
            cm0 = fmaxf(cm0, fmaxf(S[t][0], S[t][1]));
            cm1 = fmaxf(cm1, fmaxf(S[t][2], S[t][3]));
        }
        cm0 = fmaxf(cm0, __shfl_xor_sync(0xffffffffu, cm0, 1));
        cm0 = fmaxf(cm0, __shfl_xor_sync(0xffffffffu, cm0, 2));
        cm1 = fmaxf(cm1, __shfl_xor_sync(0xffffffffu, cm1, 1));
        cm1 = fmaxf(cm1, __shfl_xor_sync(0xffffffffu, cm1, 2));

        float mn0 = fmaxf(m0, cm0), mn1 = fmaxf(m1, cm1);
        float al0 = __expf(m0 - mn0), al1 = __expf(m1 - mn1);
        m0 = mn0; m1 = mn1;

        float s0 = 0.f, s1 = 0.f;
#pragma unroll
        for (int t = 0; t < 4; ++t) {
            S[t][0] = __expf(S[t][0] - mn0);
            S[t][1] = __expf(S[t][1] - mn0);
            S[t][2] = __expf(S[t][2] - mn1);
            S[t][3] = __expf(S[t][3] - mn1);
            s0 += S[t][0] + S[t][1];
            s1 += S[t][2] + S[t][3];
        }
        s0 += __shfl_xor_sync(0xffffffffu, s0, 1);
        s0 += __shfl_xor_sync(0xffffffffu, s0, 2);
        s1 += __shfl_xor_sync(0xffffffffu, s1, 1);
        s1 += __shfl_xor_sync(0xffffffffu, s1, 2);
        l0 = l0 * al0 + s0;
        l1 = l1 * al1 + s1;
#pragma unroll
        for (int n = 0; n < 8; ++n) {
            O[n][0] *= al0; O[n][1] *= al0;
            O[n][2] *= al1; O[n][3] *= al1;
        }

        const unsigned* vfp = VF + p * (4 * TSTRIDE);
        const int srcA = (lane & ~3) | (q >> 1);
        const int srcB = srcA | 2;
#pragma unroll
        for (int t = 0; t < 4; ++t) {
            unsigned p0 = cvt_tf32(S[t][0]);
            unsigned p1 = cvt_tf32(S[t][1]);
            unsigned p2 = cvt_tf32(S[t][2]);
            unsigned p3 = cvt_tf32(S[t][3]);
            unsigned u0 = __shfl_sync(0xffffffffu, p0, srcA);
            unsigned u1 = __shfl_sync(0xffffffffu, p1, srcA);
            unsigned v0s = __shfl_sync(0xffffffffu, p0, srcB);
            unsigned v1s = __shfl_sync(0xffffffffu, p1, srcB);
            unsigned w0 = __shfl_sync(0xffffffffu, p2, srcA);
            unsigned w1 = __shfl_sync(0xffffffffu, p3, srcA);
            unsigned x0 = __shfl_sync(0xffffffffu, p2, srcB);
            unsigned x1 = __shfl_sync(0xffffffffu, p3, srcB);
            unsigned a0 = (q & 1) ? u1 : u0;
            unsigned a1 = (q & 1) ? w1 : w0;
            unsigned a2 = (q & 1) ? v1s : v0s;
            unsigned a3 = (q & 1) ? x1 : x0;
            const uint4* vv = (const uint4*)&vfp[t * TSTRIDE + rb];
            uint4 v0 = vv[0], v1 = vv[1], v2 = vv[2], v3 = vv[3];
            mma_tf32(O[0], a0, a1, a2, a3, v0.x, v0.y);
            mma_tf32(O[1], a0, a1, a2, a3, v0.z, v0.w);
            mma_tf32(O[2], a0, a1, a2, a3, v1.x, v1.y);
            mma_tf32(O[3], a0, a1, a2, a3, v1.z, v1.w);
            mma_tf32(O[4], a0, a1, a2, a3, v2.x, v2.y);
            mma_tf32(O[5], a0, a1, a2, a3, v2.z, v2.w);
            mma_tf32(O[6], a0, a1, a2, a3, v3.x, v3.y);
            mma_tf32(O[7], a0, a1, a2, a3, v3.z, v3.w);
        }

        {
            const int jc = (j + 2 < 64) ? j + 2 : 63;
            const size_t roff = (size_t)(jc * 32 + wr) * DH + wc8;
            float* sk = &stK[p * STG_CHUNK + stoff];
            float* sv = &stV[p * STG_CHUNK + stoff];
            cp16(sk,     gk + roff);
            cp16(sk + 4, gk + roff + 4);
            cp16(sv,     gv + roff);
            cp16(sv + 4, gv + roff + 4);
            cp_commit();
        }
        cp_wait1();

        {
            const int jb = (j + 1 < 64) ? j + 1 : 63;
            const int j0n = jb * 32;
#pragma unroll
            for (int t = 0; t < 4; ++t) {
                float2 blo = *(const float2*)
                    &biasw[(size_t)qg       * NN + j0n + t * 8 + 2 * q];
                float2 bhi = *(const float2*)
                    &biasw[(size_t)(qg + 8) * NN + j0n + t * 8 + 2 * q];
                S[t][0] = blo.x; S[t][1] = blo.y;
                S[t][2] = bhi.x; S[t][3] = bhi.y;
            }
        }

        {
            const int pn = p ^ 1;
            const float* sk = &stK[pn * STG_CHUNK + stoff];
            const float* sv = &stV[pn * STG_CHUNK + stoff];
            float4 k0 = *(const float4*)sk;
            float4 k1 = *(const float4*)(sk + 4);
            float4 v0 = *(const float4*)sv;
            float4 v1 = *(const float4*)(sv + 4);
            unsigned* kf = KF + pn * (4 * TSTRIDE);
            unsigned* vf = VF + pn * (4 * TSTRIDE);
            kf[kdst +  0] = cvt_tf32(k0.x); kf[kdst + 20] = cvt_tf32(k0.y);
            kf[kdst + 40] = cvt_tf32(k0.z); kf[kdst + 60] = cvt_tf32(k0.w);
            kf[kdst +  1] = cvt_tf32(k1.x); kf[kdst + 21] = cvt_tf32(k1.y);
            kf[kdst + 41] = cvt_tf32(k1.z); kf[kdst + 61] = cvt_tf32(k1.w);
            vf[vdst +   0]     = cvt_tf32(v0.x);
            vf[vdst +  80]     = cvt_tf32(v0.y);
            vf[vdst + 160]     = cvt_tf32(v0.z);
            vf[vdst + 240]     = cvt_tf32(v0.w);
            vf[vdst + 320 + 8] = cvt_tf32(v1.x);
            vf[vdst + 400 + 8] = cvt_tf32(v1.y);
            vf[vdst + 480 + 8] = cvt_tf32(v1.z);
            vf[vdst + 560 + 8] = cvt_tf32(v1.w);
        }
        __syncthreads();
    }

    const float il0 = 1.f / l0, il1 = 1.f / l1;
    const int row0 = qblk + w * 16 + qg;
    const int row1 = row0 + 8;
#pragma unroll
    for (int n = 0; n < 8; ++n) {
        float2 olo = make_float2(O[n][0] * il0, O[n][1] * il0);
        float2 ohi = make_float2(O[n][2] * il1, O[n][3] * il1);
        *(float2*)&g_mid[(size_t)(b * NN + row0) * HIDDEN
                         + h * DH + n * 8 + 2 * q] = olo;
        *(float2*)&g_mid[(size_t)(b * NN + row1) * HIDDEN
                         + h * DH + n * 8 + 2 * q] = ohi;
    }
}

#define ATTN_SMEM (4 * (4 * 4 * TSTRIDE + 4 * STG_CHUNK))

// =====================================================================
extern "C" void kernel_launch(void* const* d_in, const int* in_sizes, int n_in,
                              void* d_out, int out_size)
{
    const float *x = nullptr, *bias = nullptr, *wqkv = nullptr, *wout = nullptr;
    for (int i = 0; i < n_in; ++i) {
        switch (in_sizes[i]) {
            case 4194304:  x    = (const float*)d_in[i]; break;  // x [4,2048,512]
            case 33554432: bias = (const float*)d_in[i]; break;  // pos_bias [8,2048,2048]
            case 786432:   wqkv = (const float*)d_in[i]; break;  // W_qkv [512,1536]
            case 262144:   wout = (const float*)d_in[i]; break;  // W_out [512,512]
        }
    }

    void *p_qkv = nullptr, *p_mid = nullptr;
    void *p_xp = nullptr, *p_wqh = nullptr, *p_wql = nullptr;
    void *p_mp = nullptr, *p_woh = nullptr;
    cudaGetSymbolAddress(&p_qkv, g_qkv);
    cudaGetSymbolAddress(&p_mid, g_mid);
    cudaGetSymbolAddress(&p_xp,  g_xp);
    cudaGetSymbolAddress(&p_wqh, g_wq_hi);
    cudaGetSymbolAddress(&p_wql, g_wq_lo);
    cudaGetSymbolAddress(&p_mp,  g_mp);
    cudaGetSymbolAddress(&p_woh, g_wo_hi);

    // opt-in to >48KB dynamic smem (non-stream calls: capture-safe)
    cudaFuncSetAttribute(attn_tf32,
                         cudaFuncAttributeMaxDynamicSharedMemorySize,
                         ATTN_SMEM);
    cudaFuncSetAttribute(pgemm<2>,
                         cudaFuncAttributeMaxDynamicSharedMemorySize,
                         PGEMM_SMEM_2);
    cudaFuncSetAttribute(pgemm<1>,
                         cudaFuncAttributeMaxDynamicSharedMemorySize,
                         PGEMM_SMEM_1);

    const int MR = BB * NN;   // 8192 rows

    // 0) pack x (tf32 hi) and W_qkv (exact hi+lo split)
    pack_a<<<(MR / 16) * (DIM / 8) / 8, 256>>>(x, (unsigned*)p_xp, DIM);
    pack_b<<<(THC / 8) * (DIM / 16) / 8, 256>>>(
        wqkv, (unsigned*)p_wqh, (unsigned*)p_wql, DIM, THC);

    // 1) qkv = x_hi @ (W_hi + W_lo)   [W exact; only x is tf32-rounded]
    pgemm<2><<<dim3(THC / 64, MR / 128), 256, PGEMM_SMEM_2>>>(
        (const unsigned*)p_xp, (const unsigned*)p_wqh, (const unsigned*)p_wql,
        (float*)p_qkv, MR, THC, DIM);

    // 2) split + rotary + scale
    qkv_transform<<<(BB * HEADS * NN * 32) / 256, 256>>>();

    // 3) fused flash attention (tf32 tensor cores, cp.async pipelined)
    attn_tf32<<<dim3(NN / 128, HEADS, BB), 256, ATTN_SMEM>>>(bias);

    // 4) pack mid + W_out, then out = mid_hi @ Wout_hi (1x tf32, terminal)
    pack_a<<<(MR / 16) * (HIDDEN / 8) / 8, 256>>>(
        (const float*)p_mid, (unsigned*)p_mp, HIDDEN);
    pack_b<<<(DIM / 8) * (HIDDEN / 16) / 8, 256>>>(
        wout, (unsigned*)p_woh, (unsigned*)0, HIDDEN, DIM);
    pgemm<1><<<dim3(DIM / 64, MR / 128), 256, PGEMM_SMEM_1>>>(
        (const unsigned*)p_mp, (const unsigned*)p_woh, (const unsigned*)0,
        (float*)d_out, MR, DIM, HIDDEN);
}

// round 13
// speedup vs baseline: 1.5382x; 1.0849x over previous
#include <cuda_runtime.h>
#include <math.h>

// Problem constants
#define BB 4
#define NN 2048
#define DIM 512
#define HEADS 8
#define DH 64
#define HIDDEN 512          // HEADS*DH
#define THC 1536            // 3*HIDDEN

// ---------------- scratch (device globals: allocation-free rule) ----------
__device__ float    g_qkv[(size_t)BB * NN * THC];          // 48 MB
__device__ float    g_q  [(size_t)BB * HEADS * NN * DH];   // 16 MB
// fragment-major packed operands (tf32 bit patterns)
__device__ unsigned g_kp  [(size_t)BB * HEADS * NN * DH];  // 16 MB  K packed (pack_b: dims=K, keys=N)
__device__ unsigned g_vp  [(size_t)BB * HEADS * NN * DH];  // 16 MB  V packed (pack_b: keys=K, dh=N)
__device__ unsigned g_xp  [(size_t)BB * NN * DIM];         // 16 MB  x packed
__device__ unsigned g_wq_hi[(size_t)DIM * THC];            // 3 MB
__device__ unsigned g_wq_lo[(size_t)DIM * THC];            // 3 MB
__device__ unsigned g_mp  [(size_t)BB * NN * HIDDEN];      // 16 MB  mid packed (pack_a layout)
__device__ unsigned g_wo_hi[(size_t)HIDDEN * DIM];         // 1 MB

// inv_freq[i] = 10000^(-2i/64) = 10^(-i/8), correctly-rounded fp32
__constant__ float c_invfreq[32] = {
    1.0f,
    0.74989420933245582f, 0.56234132519034907f, 0.42169650342858220f,
    0.31622776601683794f, 0.23713737056616552f, 0.17782794100389228f,
    0.13335214321633240f, 0.1f,
    0.074989420933245582f, 0.056234132519034907f, 0.042169650342858220f,
    0.031622776601683794f, 0.023713737056616552f, 0.017782794100389228f,
    0.013335214321633240f, 0.01f,
    0.0074989420933245582f, 0.0056234132519034907f, 0.0042169650342858220f,
    0.0031622776601683794f, 0.0023713737056616552f, 0.0017782794100389228f,
    0.0013335214321633240f, 0.001f,
    0.00074989420933245582f, 0.00056234132519034907f, 0.00042169650342858220f,
    0.00031622776601683794f, 0.00023713737056616552f, 0.00017782794100389228f,
    0.00013335214321633240f
};

// ---------------- tf32 helpers ----------------
__device__ __forceinline__ unsigned cvt_tf32(float f) {
    unsigned r;
    asm("cvt.rna.tf32.f32 %0, %1;" : "=r"(r) : "f"(f));
    return r;
}

__device__ __forceinline__ void mma_tf32(float c[4],
                                         unsigned a0, unsigned a1,
                                         unsigned a2, unsigned a3,
                                         unsigned b0, unsigned b1) {
    asm volatile(
        "mma.sync.aligned.m16n8k8.row.col.f32.tf32.tf32.f32 "
        "{%0,%1,%2,%3}, {%4,%5,%6,%7}, {%8,%9}, {%0,%1,%2,%3};\n"
        : "+f"(c[0]), "+f"(c[1]), "+f"(c[2]), "+f"(c[3])
        : "r"(a0), "r"(a1), "r"(a2), "r"(a3), "r"(b0), "r"(b1));
}

__device__ __forceinline__ void cp16(void* dst_smem, const void* src_gmem) {
    unsigned s = (unsigned)__cvta_generic_to_shared(dst_smem);
    asm volatile("cp.async.cg.shared.global [%0], [%1], 16;"
                 :: "r"(s), "l"(src_gmem));
}
__device__ __forceinline__ void cp_commit() {
    asm volatile("cp.async.commit_group;");
}
__device__ __forceinline__ void cp_wait1() {
    asm volatile("cp.async.wait_group 1;");
}

// =====================================================================
// Pack kernels (proven R11): m16n8k8 fragment-major tf32 layout.
// A layout [M/16][K/8][128]: word[lane*4+r]: a0=(qg,q) a1=(qg+8,q)
//   a2=(qg,q+4) a3=(qg+8,q+4).
// B layout [N/8][K/16][128]: word[lane*4+r]: r0=(k=q,n=qg) r1=(k=q+4)
//   r2=(k=8+q) r3=(k=12+q).
// =====================================================================
__global__ __launch_bounds__(256)
void pack_a(const float* __restrict__ src, unsigned* __restrict__ dst, int K)
{
    const int gw   = (blockIdx.x * 256 + threadIdx.x) >> 5;
    const int lane = threadIdx.x & 31;
    const int KB   = K >> 3;
    const int mb   = gw / KB;
    const int kb   = gw - mb * KB;
    const int qg   = lane >> 2, q = lane & 3;
    const float* s = src + (size_t)(mb * 16 + qg) * K + kb * 8 + q;
    uint4 o;
    o.x = cvt_tf32(s[0]);
    o.y = cvt_tf32(s[(size_t)8 * K]);
    o.z = cvt_tf32(s[4]);
    o.w = cvt_tf32(s[(size_t)8 * K + 4]);
    *(uint4*)&dst[(size_t)gw * 128 + lane * 4] = o;
}

__global__ __launch_bounds__(256)
void pack_b(const float* __restrict__ src, unsigned* __restrict__ hi,
            unsigned* __restrict__ lo, int K, int N)
{
    const int gw   = (blockIdx.x * 256 + threadIdx.x) >> 5;
    const int lane = threadIdx.x & 31;
    const int KB2  = K >> 4;
    const int nb   = gw / KB2;
    const int kb2  = gw - nb * KB2;
    const int qg   = lane >> 2, q = lane & 3;
    const float* s = src + (size_t)(kb2 * 16 + q) * N + nb * 8 + qg;
    float v0 = s[0], v1 = s[(size_t)4 * N], v2 = s[(size_t)8 * N],
          v3 = s[(size_t)12 * N];
    uint4 h;
    h.x = cvt_tf32(v0); h.y = cvt_tf32(v1);
    h.z = cvt_tf32(v2); h.w = cvt_tf32(v3);
    *(uint4*)&hi[(size_t)gw * 128 + lane * 4] = h;
    if (lo) {
        uint4 l;
        l.x = cvt_tf32(v0 - __uint_as_float(h.x));
        l.y = cvt_tf32(v1 - __uint_as_float(h.y));
        l.z = cvt_tf32(v2 - __uint_as_float(h.z));
        l.w = cvt_tf32(v3 - __uint_as_float(h.w));
        *(uint4*)&lo[(size_t)gw * 128 + lane * 4] = l;
    }
}

// =====================================================================
// Packed tensor-core GEMM (proven R11). PB = B planes.
// =====================================================================
#define ABUF 4096
#define BBUF 2048

template<int PB>
__global__ __launch_bounds__(256)
void pgemm(const unsigned* __restrict__ Ap, const unsigned* __restrict__ Bh,
           const unsigned* __restrict__ Bl, float* __restrict__ C,
           int M, int Nc, int K)
{
    extern __shared__ unsigned sm[];
    unsigned* As  = sm;
    unsigned* Bhs = sm + 3 * ABUF;
    unsigned* Bls = sm + 3 * ABUF + 3 * BBUF;

    const int tid  = threadIdx.x;
    const int lane = tid & 31;
    const int w    = tid >> 5;
    const int qg   = lane >> 2;
    const int q    = lane & 3;
    const int m0   = blockIdx.y * 128;
    const int n0   = blockIdx.x * 64;
    const int KB   = K >> 3;
    const int KB2  = K >> 4;
    const int NK   = K >> 5;

    const unsigned* Ag  = Ap + (size_t)(m0 >> 4) * KB * 128;
    const unsigned* Bhg = Bh + (size_t)(n0 >> 3) * KB2 * 128;
    const unsigned* Blg = (PB == 2) ? Bl + (size_t)(n0 >> 3) * KB2 * 128
                                    : (const unsigned*)0;

    const int cw  = tid >> 5;
    const int lw4 = (tid & 31) * 4;

    auto issue_tile = [&](int it, int p) {
        const unsigned* ga = Ag + ((size_t)cw * KB + it * 4) * 128;
        unsigned* da = As + p * ABUF + cw * 512;
#pragma unroll
        for (int s = 0; s < 4; ++s)
            cp16(da + s * 128 + lw4, ga + s * 128 + lw4);
        const unsigned* gb = Bhg + ((size_t)cw * KB2 + it * 2) * 128;
        unsigned* db = Bhs + p * BBUF + cw * 256;
#pragma unroll
        for (int s = 0; s < 2; ++s)
            cp16(db + s * 128 + lw4, gb + s * 128 + lw4);
        if (PB == 2) {
            const unsigned* gl = Blg + ((size_t)cw * KB2 + it * 2) * 128;
            unsigned* dl = Bls + p * BBUF + cw * 256;
#pragma unroll
            for (int s = 0; s < 2; ++s)
                cp16(dl + s * 128 + lw4, gl + s * 128 + lw4);
        }
        cp_commit();
    };

    float C_[8][4];
#pragma unroll
    for (int nt = 0; nt < 8; ++nt)
#pragma unroll
        for (int j = 0; j < 4; ++j) C_[nt][j] = 0.f;

    issue_tile(0, 0);
    issue_tile(1, 1);
    cp_wait1();
    __syncthreads();

    for (int it = 0; it < NK; ++it) {
        const int p = it % 3;
        const int itn = (it + 2 < NK) ? it + 2 : NK - 1;
        issue_tile(itn, (it + 2) % 3);

        uint4 af[4];
#pragma unroll
        for (int kk = 0; kk < 4; ++kk)
            af[kk] = *(const uint4*)&As[p * ABUF + w * 512 + kk * 128 + lane * 4];
#pragma unroll
        for (int nt = 0; nt < 8; ++nt) {
            const unsigned* bb = &Bhs[p * BBUF + nt * 256 + lane * 4];
            uint4 b0 = *(const uint4*)bb;
            uint4 b1 = *(const uint4*)(bb + 128);
            mma_tf32(C_[nt], af[0].x, af[0].y, af[0].z, af[0].w, b0.x, b0.y);
            mma_tf32(C_[nt], af[1].x, af[1].y, af[1].z, af[1].w, b0.z, b0.w);
            mma_tf32(C_[nt], af[2].x, af[2].y, af[2].z, af[2].w, b1.x, b1.y);
            mma_tf32(C_[nt], af[3].x, af[3].y, af[3].z, af[3].w, b1.z, b1.w);
            if (PB == 2) {
                const unsigned* bl = &Bls[p * BBUF + nt * 256 + lane * 4];
                uint4 l0 = *(const uint4*)bl;
                uint4 l1 = *(const uint4*)(bl + 128);
                mma_tf32(C_[nt], af[0].x, af[0].y, af[0].z, af[0].w, l0.x, l0.y);
                mma_tf32(C_[nt], af[1].x, af[1].y, af[1].z, af[1].w, l0.z, l0.w);
                mma_tf32(C_[nt], af[2].x, af[2].y, af[2].z, af[2].w, l1.x, l1.y);
                mma_tf32(C_[nt], af[3].x, af[3].y, af[3].z, af[3].w, l1.z, l1.w);
            }
        }

        cp_wait1();
        __syncthreads();
    }

#pragma unroll
    for (int nt = 0; nt < 8; ++nt) {
        int col = n0 + nt * 8 + 2 * q;
        size_t row = (size_t)(m0 + w * 16 + qg);
        *(float2*)&C[row * Nc + col]       = make_float2(C_[nt][0], C_[nt][1]);
        *(float2*)&C[(row + 8) * Nc + col] = make_float2(C_[nt][2], C_[nt][3]);
    }
}

#define PGEMM_SMEM_2 (4 * (3 * ABUF + 3 * BBUF * 2))   // 98304 B
#define PGEMM_SMEM_1 (4 * (3 * ABUF + 3 * BBUF))       // 73728 B

// =====================================================================
// QKV split + rotary (+ q scale). Q -> g_q (row-major); K, V -> packed
// fragment-major tf32 gmem (pack_b layouts; K: dims=K/keys=N,
// V: keys=K/dh=N), eliminating the attention repack entirely.
// =====================================================================
__global__ __launch_bounds__(256)
void qkv_transform()
{
    const int idx  = blockIdx.x * 256 + threadIdx.x;
    const int pair = idx & 31;
    const int n    = (idx >> 5) & (NN - 1);
    const int bh   = idx >> 16;
    const int b    = bh >> 3;
    const int h    = bh & 7;

    const float* src = g_qkv + (size_t)(b * NN + n) * THC;
    const int col = h * DH + pair * 2;

    float2 qv = *(const float2*)&src[col];
    float2 kv = *(const float2*)&src[HIDDEN + col];
    float2 vv = *(const float2*)&src[2 * HIDDEN + col];

    float fr = (float)n * c_invfreq[pair];
    float sn, cs;
    sincosf(fr, &sn, &cs);

    const float scale = 0.125f;
    float oq0 = (qv.x * cs - qv.y * sn) * scale;
    float oq1 = (qv.y * cs + qv.x * sn) * scale;
    float ok0 = kv.x * cs - kv.y * sn;
    float ok1 = kv.y * cs + kv.x * sn;

    const int d0 = pair * 2;           // even, 0..62
    const size_t bhbase = (size_t)bh * (NN * DH);

    // Q: row-major (attention loads it once)
    size_t o = bhbase + (size_t)n * DH + d0;
    g_q[o] = oq0; g_q[o + 1] = oq1;

    // K packed: element (k=d, n=key): block (key>>3)*4 + (d>>4),
    // word = (((key&7)<<2)|(d&3))*4 + ((d&15)>>2)
    {
        const int qgk = n & 7, nbk = n >> 3;
        const int kb2 = d0 >> 4;
        size_t kbase = bhbase + ((size_t)nbk * 4 + kb2) * 128;
        int w0 = ((qgk << 2) | (d0 & 3)) * 4 + ((d0 & 15) >> 2);
        int w1 = ((qgk << 2) | ((d0 + 1) & 3)) * 4 + (((d0 + 1) & 15) >> 2);
        g_kp[kbase + w0] = cvt_tf32(ok0);
        g_kp[kbase + w1] = cvt_tf32(ok1);
    }

    // V packed: element (k=key, n=d): block (d>>3)*128 + (key>>4),
    // word = (((d&7)<<2)|(key&3))*4 + ((key&15)>>2)
    {
        const int qv_ = n & 3, rv = (n & 15) >> 2, kb2v = n >> 4;
        const int nb0 = d0 >> 3, qg0 = d0 & 7;   // d0 even -> d0+1 same nb
        size_t vbase = bhbase + ((size_t)nb0 * 128 + kb2v) * 128;
        g_vp[vbase + ((qg0 << 2) | qv_) * 4 + rv]       = cvt_tf32(vv.x);
        g_vp[vbase + (((qg0 + 1) << 2) | qv_) * 4 + rv] = cvt_tf32(vv.y);
    }
}

// =====================================================================
// Fused flash attention, tf32 tensor cores, pre-packed K/V.
// grid (NN/128, HEADS, BB), block 256 (8 warps x 16 q rows), chunk = 32
// keys. 3-stage cp.async pipeline of fragment-ready 16KB chunks;
// ONE barrier per iter. Epilogue writes g_mp in pack_a layout directly.
// =====================================================================
#define CHUNK_WORDS 4096   // K 2048 + V 2048 (words)
#define ATTN_SMEM (3 * CHUNK_WORDS * 4)   // 49152 B

__global__ __launch_bounds__(256, 2)
void attn_tf32(const float* __restrict__ bias)
{
    extern __shared__ unsigned sm[];   // [3][CHUNK_WORDS]

    const int tid  = threadIdx.x;
    const int lane = tid & 31;
    const int w    = tid >> 5;
    const int qg   = lane >> 2;
    const int q    = lane & 3;
    const int qblk = blockIdx.x * 128;
    const int h    = blockIdx.y;
    const int b    = blockIdx.z;
    const int bh   = b * HEADS + h;
    const unsigned* Kbh = g_kp + (size_t)bh * (NN * DH);
    const unsigned* Vbh = g_vp + (size_t)bh * (NN * DH);
    const float* biasw = bias + (size_t)h * NN * NN
                              + (size_t)(qblk + w * 16) * NN;

    // copy mapping: K chunk contiguous 2048 words; V = 8 regions of 256
    const int koff = tid * 8;
    const int vreg = tid >> 5;
    const int voff = (tid & 31) * 8;

    auto issue_chunk = [&](int j, int p) {
        unsigned* dst = sm + p * CHUNK_WORDS;
        const unsigned* sk = Kbh + (size_t)j * 2048 + koff;
        cp16(dst + koff,     sk);
        cp16(dst + koff + 4, sk + 4);
        unsigned* dv = dst + 2048 + vreg * 256 + voff;
        const unsigned* sv = Vbh + ((size_t)vreg * 128 + j * 2) * 128 + voff;
        cp16(dv,     sv);
        cp16(dv + 4, sv + 4);
        cp_commit();
    };

    // ---- Q fragments, register-resident ----
    unsigned qa[8][4];
    {
        const float* Qp = g_q + (size_t)bh * (NN * DH)
                        + (size_t)(qblk + w * 16) * DH;
#pragma unroll
        for (int kc = 0; kc < 8; ++kc) {
            qa[kc][0] = cvt_tf32(Qp[(size_t)qg       * DH + kc * 8 + q]);
            qa[kc][1] = cvt_tf32(Qp[(size_t)(qg + 8) * DH + kc * 8 + q]);
            qa[kc][2] = cvt_tf32(Qp[(size_t)qg       * DH + kc * 8 + q + 4]);
            qa[kc][3] = cvt_tf32(Qp[(size_t)(qg + 8) * DH + kc * 8 + q + 4]);
        }
    }

    issue_chunk(0, 0);
    issue_chunk(1, 1);

    // bias chunk 0 -> S (hidden behind the cp.async wait)
    float S[4][4];
#pragma unroll
    for (int t = 0; t < 4; ++t) {
        float2 blo = *(const float2*)&biasw[(size_t)qg       * NN + t * 8 + 2 * q];
        float2 bhi = *(const float2*)&biasw[(size_t)(qg + 8) * NN + t * 8 + 2 * q];
        S[t][0] = blo.x; S[t][1] = blo.y;
        S[t][2] = bhi.x; S[t][3] = bhi.y;
    }

    cp_wait1();
    __syncthreads();

    float O[8][4];
#pragma unroll
    for (int n = 0; n < 8; ++n)
#pragma unroll
        for (int j = 0; j < 4; ++j) O[n][j] = 0.f;
    float m0 = -INFINITY, m1 = -INFINITY, l0 = 0.f, l1 = 0.f;

    const int srcA = (lane & ~3) | (q >> 1);
    const int srcB = srcA | 2;

    for (int j = 0; j < 64; ++j) {
        const int p = j % 3;
        issue_chunk((j + 2 < 64) ? j + 2 : 63, (j + 2) % 3);

        // ---- S += Q K^T (fragment-ready K) ----
        const unsigned* KF = sm + p * CHUNK_WORDS;
#pragma unroll
        for (int t = 0; t < 4; ++t) {
            uint4 k0 = *(const uint4*)&KF[t * 512 +   0 + lane * 4];
            uint4 k1 = *(const uint4*)&KF[t * 512 + 128 + lane * 4];
            uint4 k2 = *(const uint4*)&KF[t * 512 + 256 + lane * 4];
            uint4 k3 = *(const uint4*)&KF[t * 512 + 384 + lane * 4];
            mma_tf32(S[t], qa[0][0], qa[0][1], qa[0][2], qa[0][3], k0.x, k0.y);
            mma_tf32(S[t], qa[1][0], qa[1][1], qa[1][2], qa[1][3], k0.z, k0.w);
            mma_tf32(S[t], qa[2][0], qa[2][1], qa[2][2], qa[2][3], k1.x, k1.y);
            mma_tf32(S[t], qa[3][0], qa[3][1], qa[3][2], qa[3][3], k1.z, k1.w);
            mma_tf32(S[t], qa[4][0], qa[4][1], qa[4][2], qa[4][3], k2.x, k2.y);
            mma_tf32(S[t], qa[5][0], qa[5][1], qa[5][2], qa[5][3], k2.z, k2.w);
            mma_tf32(S[t], qa[6][0], qa[6][1], qa[6][2], qa[6][3], k3.x, k3.y);
            mma_tf32(S[t], qa[7][0], qa[7][1], qa[7][2], qa[7][3], k3.z, k3.w);
        }

        // ---- online softmax ----
        float cm0 = -INFINITY, cm1 = -INFINITY;
#pragma unroll
        for (int t = 0; t < 4; ++t) {
            cm0 = fmaxf(cm0, fmaxf(S[t][0], S[t][1]));
            cm1 = fmaxf(cm1, fmaxf(S[t][2], S[t][3]));
        }
        cm0 = fmaxf(cm0, __shfl_xor_sync(0xffffffffu, cm0, 1));
        cm0 = fmaxf(cm0, __shfl_xor_sync(0xffffffffu, cm0, 2));
        cm1 = fmaxf(cm1, __shfl_xor_sync(0xffffffffu, cm1, 1));
        cm1 = fmaxf(cm1, __shfl_xor_sync(0xffffffffu, cm1, 2));

        float mn0 = fmaxf(m0, cm0), mn1 = fmaxf(m1, cm1);
        float al0 = __expf(m0 - mn0), al1 = __expf(m1 - mn1);
        m0 = mn0; m1 = mn1;

        float s0 = 0.f, s1 = 0.f;
#pragma unroll
        for (int t = 0; t < 4; ++t) {
            S[t][0] = __expf(S[t][0] - mn0);
            S[t][1] = __expf(S[t][1] - mn0);
            S[t][2] = __expf(S[t][2] - mn1);
            S[t][3] = __expf(S[t][3] - mn1);
            s0 += S[t][0] + S[t][1];
            s1 += S[t][2] + S[t][3];
        }
        s0 += __shfl_xor_sync(0xffffffffu, s0, 1);
        s0 += __shfl_xor_sync(0xffffffffu, s0, 2);
        s1 += __shfl_xor_sync(0xffffffffu, s1, 1);
        s1 += __shfl_xor_sync(0xffffffffu, s1, 2);
        l0 = l0 * al0 + s0;
        l1 = l1 * al1 + s1;
#pragma unroll
        for (int n = 0; n < 8; ++n) {
            O[n][0] *= al0; O[n][1] *= al0;
            O[n][2] *= al1; O[n][3] *= al1;
        }

        // ---- P fragments via quad shuffles (all 4 key-chunks) ----
        unsigned pf[4][4];
#pragma unroll
        for (int t = 0; t < 4; ++t) {
            unsigned p0 = cvt_tf32(S[t][0]);
            unsigned p1 = cvt_tf32(S[t][1]);
            unsigned p2 = cvt_tf32(S[t][2]);
            unsigned p3 = cvt_tf32(S[t][3]);
            unsigned u0 = __shfl_sync(0xffffffffu, p0, srcA);
            unsigned u1 = __shfl_sync(0xffffffffu, p1, srcA);
            unsigned v0 = __shfl_sync(0xffffffffu, p0, srcB);
            unsigned v1 = __shfl_sync(0xffffffffu, p1, srcB);
            unsigned w0 = __shfl_sync(0xffffffffu, p2, srcA);
            unsigned w1 = __shfl_sync(0xffffffffu, p3, srcA);
            unsigned x0 = __shfl_sync(0xffffffffu, p2, srcB);
            unsigned x1 = __shfl_sync(0xffffffffu, p3, srcB);
            pf[t][0] = (q & 1) ? u1 : u0;
            pf[t][1] = (q & 1) ? w1 : w0;
            pf[t][2] = (q & 1) ? v1 : v0;
            pf[t][3] = (q & 1) ? x1 : x0;
        }

        // ---- O += P @ V (fragment-ready V) ----
        const unsigned* VF = sm + p * CHUNK_WORDS + 2048;
#pragma unroll
        for (int nt = 0; nt < 8; ++nt) {
            uint4 v0 = *(const uint4*)&VF[nt * 256 +   0 + lane * 4];
            uint4 v1 = *(const uint4*)&VF[nt * 256 + 128 + lane * 4];
            mma_tf32(O[nt], pf[0][0], pf[0][1], pf[0][2], pf[0][3], v0.x, v0.y);
            mma_tf32(O[nt], pf[1][0], pf[1][1], pf[1][2], pf[1][3], v0.z, v0.w);
            mma_tf32(O[nt], pf[2][0], pf[2][1], pf[2][2], pf[2][3], v1.x, v1.y);
            mma_tf32(O[nt], pf[3][0], pf[3][1], pf[3][2], pf[3][3], v1.z, v1.w);
        }

        // ---- bias chunk j+1 -> S ----
        {
            const int j0n = ((j + 1 < 64) ? j + 1 : 63) * 32;
#pragma unroll
            for (int t = 0; t < 4; ++t) {
                float2 blo = *(const float2*)
                    &biasw[(size_t)qg       * NN + j0n + t * 8 + 2 * q];
                float2 bhi = *(const float2*)
                    &biasw[(size_t)(qg + 8) * NN + j0n + t * 8 + 2 * q];
                S[t][0] = blo.x; S[t][1] = blo.y;
                S[t][2] = bhi.x; S[t][3] = bhi.y;
            }
        }

        cp_wait1();
        __syncthreads();
    }

    // ---- epilogue: /l, refragment to pack_a layout, write g_mp ----
    const float il0 = 1.f / l0, il1 = 1.f / l1;
    const int mb = (b * NN + qblk + w * 16) >> 4;   // FIXED: include batch row offset
#pragma unroll
    for (int nt = 0; nt < 8; ++nt) {
        unsigned f0 = __float_as_uint(O[nt][0] * il0);
        unsigned f1 = __float_as_uint(O[nt][1] * il0);
        unsigned f2 = __float_as_uint(O[nt][2] * il1);
        unsigned f3 = __float_as_uint(O[nt][3] * il1);
        unsigned u0 = __shfl_sync(0xffffffffu, f0, srcA);
        unsigned u1 = __shfl_sync(0xffffffffu, f1, srcA);
        unsigned w0 = __shfl_sync(0xffffffffu, f2, srcA);
        unsigned w1 = __shfl_sync(0xffffffffu, f3, srcA);
        unsigned x0 = __shfl_sync(0xffffffffu, f0, srcB);
        unsigned x1 = __shfl_sync(0xffffffffu, f1, srcB);
        unsigned y0 = __shfl_sync(0xffffffffu, f2, srcB);
        unsigned y1 = __shfl_sync(0xffffffffu, f3, srcB);
        uint4 o;
        o.x = cvt_tf32(__uint_as_float((q & 1) ? u1 : u0));  // (qg,   q)
        o.y = cvt_tf32(__uint_as_float((q & 1) ? w1 : w0));  // (qg+8, q)
        o.z = cvt_tf32(__uint_as_float((q & 1) ? x1 : x0));  // (qg,   q+4)
        o.w = cvt_tf32(__uint_as_float((q & 1) ? y1 : y0));  // (qg+8, q+4)
        const int kb = h * 8 + nt;   // HIDDEN col block
        *(uint4*)&g_mp[((size_t)mb * (HIDDEN / 8) + kb) * 128 + lane * 4] = o;
    }
}

// =====================================================================
extern "C" void kernel_launch(void* const* d_in, const int* in_sizes, int n_in,
                              void* d_out, int out_size)
{
    const float *x = nullptr, *bias = nullptr, *wqkv = nullptr, *wout = nullptr;
    for (int i = 0; i < n_in; ++i) {
        switch (in_sizes[i]) {
            case 4194304:  x    = (const float*)d_in[i]; break;  // x [4,2048,512]
            case 33554432: bias = (const float*)d_in[i]; break;  // pos_bias [8,2048,2048]
            case 786432:   wqkv = (const float*)d_in[i]; break;  // W_qkv [512,1536]
            case 262144:   wout = (const float*)d_in[i]; break;  // W_out [512,512]
        }
    }

    void *p_qkv = nullptr;
    void *p_xp = nullptr, *p_wqh = nullptr, *p_wql = nullptr;
    void *p_mp = nullptr, *p_woh = nullptr;
    cudaGetSymbolAddress(&p_qkv, g_qkv);
    cudaGetSymbolAddress(&p_xp,  g_xp);
    cudaGetSymbolAddress(&p_wqh, g_wq_hi);
    cudaGetSymbolAddress(&p_wql, g_wq_lo);
    cudaGetSymbolAddress(&p_mp,  g_mp);
    cudaGetSymbolAddress(&p_woh, g_wo_hi);

    // opt-in to >48KB dynamic smem (non-stream calls: capture-safe)
    cudaFuncSetAttribute(attn_tf32,
                         cudaFuncAttributeMaxDynamicSharedMemorySize,
                         ATTN_SMEM);
    cudaFuncSetAttribute(pgemm<2>,
                         cudaFuncAttributeMaxDynamicSharedMemorySize,
                         PGEMM_SMEM_2);
    cudaFuncSetAttribute(pgemm<1>,
                         cudaFuncAttributeMaxDynamicSharedMemorySize,
                         PGEMM_SMEM_1);

    const int MR = BB * NN;   // 8192 rows

    // 0) pack x (tf32 hi) and W_qkv (exact hi+lo split)
    pack_a<<<(MR / 16) * (DIM / 8) / 8, 256>>>(x, (unsigned*)p_xp, DIM);
    pack_b<<<(THC / 8) * (DIM / 16) / 8, 256>>>(
        wqkv, (unsigned*)p_wqh, (unsigned*)p_wql, DIM, THC);

    // 1) qkv = x_hi @ (W_hi + W_lo)
    pgemm<2><<<dim3(THC / 64, MR / 128), 256, PGEMM_SMEM_2>>>(
        (const unsigned*)p_xp, (const unsigned*)p_wqh, (const unsigned*)p_wql,
        (float*)p_qkv, MR, THC, DIM);

    // 2) split + rotary + scale; K/V written fragment-major packed
    qkv_transform<<<(BB * HEADS * NN * 32) / 256, 256>>>();

    // 3) fused flash attention (pre-packed K/V, 3-stage cp.async);
    //    writes packed mid directly
    attn_tf32<<<dim3(NN / 128, HEADS, BB), 256, ATTN_SMEM>>>(bias);

    // 4) out = mid_hi @ Wout_hi (1x tf32, terminal)
    pack_b<<<(DIM / 8) * (HIDDEN / 16) / 8, 256>>>(
        wout, (unsigned*)p_woh, (unsigned*)0, HIDDEN, DIM);
    pgemm<1><<<dim3(DIM / 64, MR / 128), 256, PGEMM_SMEM_1>>>(
        (const unsigned*)p_mp, (const unsigned*)p_woh, (const unsigned*)0,
        (float*)d_out, MR, DIM, HIDDEN);
}